// round 1
// baseline (speedup 1.0000x reference)
#include <cuda_runtime.h>
#include <cuda_bf16.h>
#include <math.h>

// Problem constants
#define B_   2
#define N_   2048
#define DIN  2048
#define DOUT 2048
#define H_   32
#define KV_  8
#define G_   4
#define DH_  64
#define M_   (B_ * N_)          // 4096 flattened rows
#define KVD  (KV_ * DH_)        // 512

// -------- scratch (allocation-free rule: __device__ globals) --------
__device__ float g_Q[(size_t)M_ * DOUT];   // 33.5 MB
__device__ float g_K[(size_t)M_ * KVD];    //  8.4 MB
__device__ float g_V[(size_t)M_ * KVD];    //  8.4 MB
__device__ float g_ctx[(size_t)M_ * DOUT]; // 33.5 MB

// ===================================================================
// SGEMM: C[M,Nc] = A[M,K] @ B[K,Nc] (+ bias per column)
// 128x128 block tile, TBK=8, 256 threads, 8x8 per-thread micro-tile
// Requires M%128==0, Nc%128==0, K%8==0 (true for all our shapes)
// ===================================================================
#define TBM 128
#define TBN 128
#define TBK 8

__global__ __launch_bounds__(256)
void sgemm_kernel(const float* __restrict__ A, const float* __restrict__ B,
                  float* __restrict__ C, const float* __restrict__ bias,
                  int M, int Nc, int K)
{
    __shared__ float As[TBK][TBM];
    __shared__ float Bs[TBK][TBN];

    const int tid  = threadIdx.x;
    const int brow = blockIdx.y;
    const int bcol = blockIdx.x;
    const int tx   = tid & 15;       // 0..15  -> 8 cols each
    const int ty   = tid >> 4;       // 0..15  -> 8 rows each

    // A tile loader: 128 rows x 8 k -> one float4 per thread
    const int aRow = tid >> 1;
    const int aCol = (tid & 1) * 4;
    // B tile loader: 8 k x 128 cols -> one float4 per thread
    const int bRow = tid >> 5;
    const int bCol = (tid & 31) * 4;

    const float* Ag = A + (size_t)(brow * TBM + aRow) * K + aCol;
    const float* Bg = B + (size_t)bRow * Nc + bcol * TBN + bCol;

    float acc[8][8];
#pragma unroll
    for (int i = 0; i < 8; i++)
#pragma unroll
        for (int j = 0; j < 8; j++) acc[i][j] = 0.0f;

    for (int k0 = 0; k0 < K; k0 += TBK) {
        float4 av = *(const float4*)Ag;  Ag += TBK;
        float4 bv = *(const float4*)Bg;  Bg += (size_t)TBK * Nc;

        As[aCol + 0][aRow] = av.x;
        As[aCol + 1][aRow] = av.y;
        As[aCol + 2][aRow] = av.z;
        As[aCol + 3][aRow] = av.w;
        *(float4*)&Bs[bRow][bCol] = bv;
        __syncthreads();

#pragma unroll
        for (int kk = 0; kk < TBK; kk++) {
            float a[8], bb[8];
            float4 a0 = *(const float4*)&As[kk][ty * 8];
            float4 a1 = *(const float4*)&As[kk][ty * 8 + 4];
            float4 b0 = *(const float4*)&Bs[kk][tx * 8];
            float4 b1 = *(const float4*)&Bs[kk][tx * 8 + 4];
            a[0]=a0.x; a[1]=a0.y; a[2]=a0.z; a[3]=a0.w;
            a[4]=a1.x; a[5]=a1.y; a[6]=a1.z; a[7]=a1.w;
            bb[0]=b0.x; bb[1]=b0.y; bb[2]=b0.z; bb[3]=b0.w;
            bb[4]=b1.x; bb[5]=b1.y; bb[6]=b1.z; bb[7]=b1.w;
#pragma unroll
            for (int i = 0; i < 8; i++)
#pragma unroll
                for (int j = 0; j < 8; j++)
                    acc[i][j] += a[i] * bb[j];
        }
        __syncthreads();
    }

    // Epilogue
#pragma unroll
    for (int i = 0; i < 8; i++) {
        int row = brow * TBM + ty * 8 + i;
        float* cp = C + (size_t)row * Nc + bcol * TBN + tx * 8;
        if (bias) {
            const float* bp = bias + bcol * TBN + tx * 8;
#pragma unroll
            for (int j = 0; j < 8; j++) acc[i][j] += bp[j];
        }
        float4 o0 = make_float4(acc[i][0], acc[i][1], acc[i][2], acc[i][3]);
        float4 o1 = make_float4(acc[i][4], acc[i][5], acc[i][6], acc[i][7]);
        *(float4*)cp       = o0;
        *(float4*)(cp + 4) = o1;
    }
}

// ===================================================================
// Flash attention (causal, GQA). One block = 128 query rows of one
// (batch, head). One thread = one query row; online softmax; K/V tiles
// of 32 keys staged in smem (broadcast LDS.128 reads).
// ===================================================================
#define FA_BM 128
#define FA_BN 32

__global__ __launch_bounds__(128)
void flash_kernel(const float* __restrict__ Q, const float* __restrict__ Km,
                  const float* __restrict__ Vm, float* __restrict__ ctx)
{
    const int tid = threadIdx.x;
    const int m0  = blockIdx.x * FA_BM;
    const int h   = blockIdx.y;
    const int kv  = h >> 2;          // G_=4
    const int b   = blockIdx.z;
    const int row = m0 + tid;        // query position within the sequence

    __shared__ float Ks[FA_BN][DH_];
    __shared__ float Vs[FA_BN][DH_];

    // Load this thread's query row into registers
    float q[DH_];
    const float* qp = Q + ((size_t)(b * N_ + row)) * DOUT + h * DH_;
#pragma unroll
    for (int i = 0; i < DH_ / 4; i++) {
        float4 v = ((const float4*)qp)[i];
        q[4*i+0] = v.x; q[4*i+1] = v.y; q[4*i+2] = v.z; q[4*i+3] = v.w;
    }

    float acc[DH_];
#pragma unroll
    for (int d = 0; d < DH_; d++) acc[d] = 0.0f;
    float mrow = -INFINITY;
    float lrow = 0.0f;
    const float scale = 0.125f;      // 1/sqrt(64)

    const int kend = m0 + FA_BM;     // causal: keys needed up to last row of tile
    for (int n0 = 0; n0 < kend; n0 += FA_BN) {
        // Cooperative tile load: 32x64 floats each = 512 float4; 128 thr * 4
        const float* kbase = Km + ((size_t)(b * N_ + n0)) * KVD + kv * DH_;
        const float* vbase = Vm + ((size_t)(b * N_ + n0)) * KVD + kv * DH_;
#pragma unroll
        for (int i = 0; i < 4; i++) {
            int idx = tid + i * 128;        // float4 index
            int r = idx >> 4;               // 16 float4 per 64-float row
            int c = (idx & 15) * 4;
            *(float4*)&Ks[r][c] = *(const float4*)(kbase + (size_t)r * KVD + c);
            *(float4*)&Vs[r][c] = *(const float4*)(vbase + (size_t)r * KVD + c);
        }
        __syncthreads();

        // Scores for this tile
        float s[FA_BN];
        float smax = -INFINITY;
#pragma unroll
        for (int j = 0; j < FA_BN; j++) {
            float dot = 0.0f;
#pragma unroll
            for (int d4 = 0; d4 < DH_ / 4; d4++) {
                float4 kvv = *(const float4*)&Ks[j][d4 * 4];
                dot += q[4*d4+0] * kvv.x + q[4*d4+1] * kvv.y
                     + q[4*d4+2] * kvv.z + q[4*d4+3] * kvv.w;
            }
            dot *= scale;
            if (n0 + j > row) dot = -INFINITY;   // causal mask
            s[j] = dot;
            smax = fmaxf(smax, dot);
        }

        // Online softmax update
        float mnew = fmaxf(mrow, smax);          // finite after first tile (key 0 valid)
        float corr = __expf(mrow - mnew);        // exp(-inf)=0 on first tile
        lrow *= corr;
#pragma unroll
        for (int d = 0; d < DH_; d++) acc[d] *= corr;

#pragma unroll
        for (int j = 0; j < FA_BN; j++) {
            float p = __expf(s[j] - mnew);       // masked -> exp(-inf)=0
            lrow += p;
#pragma unroll
            for (int d4 = 0; d4 < DH_ / 4; d4++) {
                float4 vv = *(const float4*)&Vs[j][d4 * 4];
                acc[4*d4+0] += p * vv.x;
                acc[4*d4+1] += p * vv.y;
                acc[4*d4+2] += p * vv.z;
                acc[4*d4+3] += p * vv.w;
            }
        }
        mrow = mnew;
        __syncthreads();
    }

    const float inv = 1.0f / lrow;               // lrow>0: diagonal key always present
    float* op = ctx + ((size_t)(b * N_ + row)) * DOUT + h * DH_;
#pragma unroll
    for (int d4 = 0; d4 < DH_ / 4; d4++) {
        float4 o = make_float4(acc[4*d4+0] * inv, acc[4*d4+1] * inv,
                               acc[4*d4+2] * inv, acc[4*d4+3] * inv);
        ((float4*)op)[d4] = o;
    }
}

// ===================================================================
// Launch
// ===================================================================
extern "C" void kernel_launch(void* const* d_in, const int* in_sizes, int n_in,
                              void* d_out, int out_size)
{
    const float* x  = (const float*)d_in[0];   // [B, N, DIN]
    const float* Wq = (const float*)d_in[1];   // [DIN, H*DH]
    const float* Wk = (const float*)d_in[2];   // [DIN, KV*DH]
    const float* Wv = (const float*)d_in[3];   // [DIN, KV*DH]
    const float* Wo = (const float*)d_in[4];   // [DOUT, DIN]
    const float* bo = (const float*)d_in[5];   // [DIN]
    float* out = (float*)d_out;                // [B, N, DIN]

    float *Q, *K, *V, *Ctx;
    cudaGetSymbolAddress((void**)&Q,   g_Q);
    cudaGetSymbolAddress((void**)&K,   g_K);
    cudaGetSymbolAddress((void**)&V,   g_V);
    cudaGetSymbolAddress((void**)&Ctx, g_ctx);

    // Projections
    sgemm_kernel<<<dim3(DOUT / TBN, M_ / TBM), 256>>>(x, Wq, Q, nullptr, M_, DOUT, DIN);
    sgemm_kernel<<<dim3(KVD  / TBN, M_ / TBM), 256>>>(x, Wk, K, nullptr, M_, KVD,  DIN);
    sgemm_kernel<<<dim3(KVD  / TBN, M_ / TBM), 256>>>(x, Wv, V, nullptr, M_, KVD,  DIN);

    // Attention
    flash_kernel<<<dim3(N_ / FA_BM, H_, B_), 128>>>(Q, K, V, Ctx);

    // Output projection + bias
    sgemm_kernel<<<dim3(DIN / TBN, M_ / TBM), 256>>>(Ctx, Wo, out, bo, M_, DIN, DOUT);
}

// round 2
// speedup vs baseline: 1.8586x; 1.8586x over previous
#include <cuda_runtime.h>
#include <math.h>

// Problem constants
#define B_   2
#define N_   2048
#define DIN  2048
#define DOUT 2048
#define H_   32
#define KV_  8
#define DH_  64
#define M_   (B_ * N_)          // 4096
#define KVD  (KV_ * DH_)        // 512

// -------- scratch (allocation-free rule: __device__ globals) --------
__device__ float g_Q[(size_t)M_ * DOUT];
__device__ float g_K[(size_t)M_ * KVD];
__device__ float g_V[(size_t)M_ * KVD];
__device__ float g_ctx[(size_t)M_ * DOUT];

// ---------------- tf32 helpers ----------------
__device__ __forceinline__ unsigned f2tf(float x) {
    unsigned r;
    asm("cvt.rna.tf32.f32 %0, %1;" : "=r"(r) : "f"(x));
    return r;
}
// split x into hi (tf32) and lo (tf32 of residual); both returned as raw bit floats
__device__ __forceinline__ void tf32_split(float x, float& hi, float& lo) {
    unsigned h = f2tf(x);
    float hf = __uint_as_float(h);
    unsigned l = f2tf(x - hf);
    hi = hf;
    lo = __uint_as_float(l);
}

__device__ __forceinline__ void mma8(float c[4], unsigned a0, unsigned a1, unsigned a2, unsigned a3,
                                     unsigned b0, unsigned b1) {
    asm volatile(
        "mma.sync.aligned.m16n8k8.row.col.f32.tf32.tf32.f32 "
        "{%0,%1,%2,%3}, {%4,%5,%6,%7}, {%8,%9}, {%0,%1,%2,%3};"
        : "+f"(c[0]), "+f"(c[1]), "+f"(c[2]), "+f"(c[3])
        : "r"(a0), "r"(a1), "r"(a2), "r"(a3), "r"(b0), "r"(b1));
}

// ===================================================================
// 3xTF32 GEMM: C[M,Nc] = A[M,K] @ B[K,Nc] (+bias)
// block 128x128, KT=16, 8 warps (2x4), warp tile 64x32
// ===================================================================
#define KT  16
#define AST 20     // stride ≡ 4 mod 32 -> conflict-free a-frag reads
#define BST 132    // stride ≡ 4 mod 32 -> conflict-free b-frag reads

__global__ __launch_bounds__(256)
void gemm3t(const float* __restrict__ A, const float* __restrict__ Bm,
            float* __restrict__ C, const float* __restrict__ bias,
            int M, int Nc, int K)
{
    __shared__ float Ah[128][AST], Al[128][AST];
    __shared__ float Bh[KT][BST],  Bl[KT][BST];

    const int tid  = threadIdx.x;
    const int lane = tid & 31;
    const int wid  = tid >> 5;
    const int wr   = (wid >> 2) * 64;   // warp row offset in tile
    const int wc   = (wid & 3) * 32;    // warp col offset in tile
    const int brow = blockIdx.y * 128;
    const int bcol = blockIdx.x * 128;

    float acc[4][4][4];
#pragma unroll
    for (int i = 0; i < 4; i++)
#pragma unroll
        for (int j = 0; j < 4; j++)
#pragma unroll
            for (int e = 0; e < 4; e++) acc[i][j][e] = 0.0f;

    for (int k0 = 0; k0 < K; k0 += KT) {
        // load A tile: 128x16 floats = 512 float4, 2 per thread
#pragma unroll
        for (int p = 0; p < 2; p++) {
            int id = tid + p * 256;
            int r = id >> 2;
            int c = (id & 3) * 4;
            float4 v = *(const float4*)(A + (size_t)(brow + r) * K + k0 + c);
            tf32_split(v.x, Ah[r][c+0], Al[r][c+0]);
            tf32_split(v.y, Ah[r][c+1], Al[r][c+1]);
            tf32_split(v.z, Ah[r][c+2], Al[r][c+2]);
            tf32_split(v.w, Ah[r][c+3], Al[r][c+3]);
        }
        // load B tile: 16x128 floats = 512 float4, 2 per thread
#pragma unroll
        for (int p = 0; p < 2; p++) {
            int id = tid + p * 256;
            int r = id >> 5;
            int c = (id & 31) * 4;
            float4 v = *(const float4*)(Bm + (size_t)(k0 + r) * Nc + bcol + c);
            tf32_split(v.x, Bh[r][c+0], Bl[r][c+0]);
            tf32_split(v.y, Bh[r][c+1], Bl[r][c+1]);
            tf32_split(v.z, Bh[r][c+2], Bl[r][c+2]);
            tf32_split(v.w, Bh[r][c+3], Bl[r][c+3]);
        }
        __syncthreads();

#pragma unroll
        for (int ks = 0; ks < KT; ks += 8) {
            unsigned ah[4][4], al[4][4], bh[4][2], bl[4][2];
#pragma unroll
            for (int mt = 0; mt < 4; mt++) {
                int r = wr + mt * 16 + (lane >> 2);
                int c = ks + (lane & 3);
                ah[mt][0] = __float_as_uint(Ah[r][c]);
                ah[mt][1] = __float_as_uint(Ah[r+8][c]);
                ah[mt][2] = __float_as_uint(Ah[r][c+4]);
                ah[mt][3] = __float_as_uint(Ah[r+8][c+4]);
                al[mt][0] = __float_as_uint(Al[r][c]);
                al[mt][1] = __float_as_uint(Al[r+8][c]);
                al[mt][2] = __float_as_uint(Al[r][c+4]);
                al[mt][3] = __float_as_uint(Al[r+8][c+4]);
            }
#pragma unroll
            for (int nt = 0; nt < 4; nt++) {
                int r = ks + (lane & 3);
                int c = wc + nt * 8 + (lane >> 2);
                bh[nt][0] = __float_as_uint(Bh[r][c]);
                bh[nt][1] = __float_as_uint(Bh[r+4][c]);
                bl[nt][0] = __float_as_uint(Bl[r][c]);
                bl[nt][1] = __float_as_uint(Bl[r+4][c]);
            }
#pragma unroll
            for (int mt = 0; mt < 4; mt++)
#pragma unroll
                for (int nt = 0; nt < 4; nt++) {
                    mma8(acc[mt][nt], ah[mt][0], ah[mt][1], ah[mt][2], ah[mt][3], bh[nt][0], bh[nt][1]);
                    mma8(acc[mt][nt], ah[mt][0], ah[mt][1], ah[mt][2], ah[mt][3], bl[nt][0], bl[nt][1]);
                    mma8(acc[mt][nt], al[mt][0], al[mt][1], al[mt][2], al[mt][3], bh[nt][0], bh[nt][1]);
                }
        }
        __syncthreads();
    }

    // epilogue
#pragma unroll
    for (int mt = 0; mt < 4; mt++) {
#pragma unroll
        for (int nt = 0; nt < 4; nt++) {
            int row = brow + wr + mt * 16 + (lane >> 2);
            int col = bcol + wc + nt * 8 + 2 * (lane & 3);
            float b0 = 0.f, b1 = 0.f;
            if (bias) { b0 = bias[col]; b1 = bias[col + 1]; }
            float2 v0 = make_float2(acc[mt][nt][0] + b0, acc[mt][nt][1] + b1);
            float2 v1 = make_float2(acc[mt][nt][2] + b0, acc[mt][nt][3] + b1);
            *(float2*)(C + (size_t)row * Nc + col)       = v0;
            *(float2*)(C + (size_t)(row + 8) * Nc + col) = v1;
        }
    }
}

// ===================================================================
// Flash attention on tensor cores. Block = 64 q rows of one (b, h).
// 4 warps x 16 rows. Key tiles of 32. Scores 3xTF32, PV 1xTF32.
// Softmax in base-2 domain (0.125*log2e folded into Q).
// ===================================================================
#define FBM 64
#define FBN 32
#define KST 68   // ≡4 mod 32
#define VST 72   // ≡8 mod 32 -> conflict-free V b-frag reads
#define PST 36   // ≡4 mod 32

__global__ __launch_bounds__(128)
void flash_mma(const float* __restrict__ Qm, const float* __restrict__ Km,
               const float* __restrict__ Vm, float* __restrict__ ctx)
{
    __shared__ float Kh[FBN][KST], Kl[FBN][KST];
    __shared__ float Vs[FBN][VST];
    __shared__ float Ps[FBM][PST];

    const int tid  = threadIdx.x;
    const int lane = tid & 31;
    const int wid  = tid >> 5;
    const int m0   = blockIdx.x * FBM;
    const int h    = blockIdx.y;
    const int b    = blockIdx.z;
    const int kv   = h >> 2;

    const int r0 = m0 + wid * 16 + (lane >> 2);   // first owned row
    const float qscale = 0.125f * 1.44269504f;    // scale * log2(e)

    // Q fragments (hi/lo), persistent: 8 k-steps over DH=64
    unsigned qh[8][4], ql[8][4];
    {
        const float* qbase = Qm + (size_t)(b * N_ ) * DOUT + h * DH_;
#pragma unroll
        for (int ks = 0; ks < 8; ks++) {
            int c = ks * 8 + (lane & 3);
            float v0 = qbase[(size_t)r0 * DOUT + c]       * qscale;
            float v1 = qbase[(size_t)(r0+8) * DOUT + c]   * qscale;
            float v2 = qbase[(size_t)r0 * DOUT + c + 4]   * qscale;
            float v3 = qbase[(size_t)(r0+8) * DOUT + c+4] * qscale;
            float hi, lo;
            tf32_split(v0, hi, lo); qh[ks][0] = __float_as_uint(hi); ql[ks][0] = __float_as_uint(lo);
            tf32_split(v1, hi, lo); qh[ks][1] = __float_as_uint(hi); ql[ks][1] = __float_as_uint(lo);
            tf32_split(v2, hi, lo); qh[ks][2] = __float_as_uint(hi); ql[ks][2] = __float_as_uint(lo);
            tf32_split(v3, hi, lo); qh[ks][3] = __float_as_uint(hi); ql[ks][3] = __float_as_uint(lo);
        }
    }

    float oacc[8][4];
#pragma unroll
    for (int d = 0; d < 8; d++)
#pragma unroll
        for (int e = 0; e < 4; e++) oacc[d][e] = 0.0f;
    float mcur0 = -1e30f, mcur1 = -1e30f, l0 = 0.0f, l1 = 0.0f;

    const int rowmax = m0 + wid * 16 + 15;
    const int nend = m0 + FBM;

    for (int n0 = 0; n0 < nend; n0 += FBN) {
        // cooperative K/V tile load: 32x64 each -> 4 float4 per thread per tensor
        const float* kbase = Km + (size_t)(b * N_ + n0) * KVD + kv * DH_;
        const float* vbase = Vm + (size_t)(b * N_ + n0) * KVD + kv * DH_;
#pragma unroll
        for (int p = 0; p < 4; p++) {
            int id = tid + p * 128;
            int r = id >> 4;
            int c = (id & 15) * 4;
            float4 kvv = *(const float4*)(kbase + (size_t)r * KVD + c);
            tf32_split(kvv.x, Kh[r][c+0], Kl[r][c+0]);
            tf32_split(kvv.y, Kh[r][c+1], Kl[r][c+1]);
            tf32_split(kvv.z, Kh[r][c+2], Kl[r][c+2]);
            tf32_split(kvv.w, Kh[r][c+3], Kl[r][c+3]);
            float4 vv = *(const float4*)(vbase + (size_t)r * KVD + c);
            Vs[r][c+0] = __uint_as_float(f2tf(vv.x));
            Vs[r][c+1] = __uint_as_float(f2tf(vv.y));
            Vs[r][c+2] = __uint_as_float(f2tf(vv.z));
            Vs[r][c+3] = __uint_as_float(f2tf(vv.w));
        }
        __syncthreads();

        if (n0 <= rowmax) {
            // ---- scores S = Q K^T (3xTF32), 4 n-subtiles of 8 ----
            float s[4][4];
#pragma unroll
            for (int nt = 0; nt < 4; nt++)
#pragma unroll
                for (int e = 0; e < 4; e++) s[nt][e] = 0.0f;

#pragma unroll
            for (int ks = 0; ks < 8; ks++) {
                unsigned bh[4][2], bl[4][2];
#pragma unroll
                for (int nt = 0; nt < 4; nt++) {
                    int n = nt * 8 + (lane >> 2);
                    int d = ks * 8 + (lane & 3);
                    bh[nt][0] = __float_as_uint(Kh[n][d]);
                    bh[nt][1] = __float_as_uint(Kh[n][d+4]);
                    bl[nt][0] = __float_as_uint(Kl[n][d]);
                    bl[nt][1] = __float_as_uint(Kl[n][d+4]);
                }
#pragma unroll
                for (int nt = 0; nt < 4; nt++) {
                    mma8(s[nt], qh[ks][0], qh[ks][1], qh[ks][2], qh[ks][3], bh[nt][0], bh[nt][1]);
                    mma8(s[nt], qh[ks][0], qh[ks][1], qh[ks][2], qh[ks][3], bl[nt][0], bl[nt][1]);
                    mma8(s[nt], ql[ks][0], ql[ks][1], ql[ks][2], ql[ks][3], bh[nt][0], bh[nt][1]);
                }
            }

            // ---- causal mask + row max ----
            float mt0 = -1e30f, mt1 = -1e30f;
#pragma unroll
            for (int nt = 0; nt < 4; nt++) {
#pragma unroll
                for (int e = 0; e < 2; e++) {
                    int col = n0 + nt * 8 + 2 * (lane & 3) + e;
                    if (col > r0)     s[nt][e]   = -1e30f;
                    if (col > r0 + 8) s[nt][2+e] = -1e30f;
                    mt0 = fmaxf(mt0, s[nt][e]);
                    mt1 = fmaxf(mt1, s[nt][2+e]);
                }
            }
            mt0 = fmaxf(mt0, __shfl_xor_sync(0xffffffff, mt0, 1));
            mt0 = fmaxf(mt0, __shfl_xor_sync(0xffffffff, mt0, 2));
            mt1 = fmaxf(mt1, __shfl_xor_sync(0xffffffff, mt1, 1));
            mt1 = fmaxf(mt1, __shfl_xor_sync(0xffffffff, mt1, 2));

            float mn0 = fmaxf(mcur0, mt0);
            float mn1 = fmaxf(mcur1, mt1);
            float cr0 = exp2f(mcur0 - mn0);
            float cr1 = exp2f(mcur1 - mn1);
            l0 *= cr0; l1 *= cr1;
#pragma unroll
            for (int d = 0; d < 8; d++) {
                oacc[d][0] *= cr0; oacc[d][1] *= cr0;
                oacc[d][2] *= cr1; oacc[d][3] *= cr1;
            }

            int prow = wid * 16 + (lane >> 2);
#pragma unroll
            for (int nt = 0; nt < 4; nt++) {
                int pc = nt * 8 + 2 * (lane & 3);
                float p00 = exp2f(s[nt][0] - mn0);
                float p01 = exp2f(s[nt][1] - mn0);
                float p10 = exp2f(s[nt][2] - mn1);
                float p11 = exp2f(s[nt][3] - mn1);
                l0 += p00 + p01;
                l1 += p10 + p11;
                Ps[prow][pc]       = __uint_as_float(f2tf(p00));
                Ps[prow][pc+1]     = __uint_as_float(f2tf(p01));
                Ps[prow+8][pc]     = __uint_as_float(f2tf(p10));
                Ps[prow+8][pc+1]   = __uint_as_float(f2tf(p11));
            }
            mcur0 = mn0; mcur1 = mn1;
            __syncwarp();

            // ---- O += P V (1xTF32), key dim 32 = 4 k-steps ----
#pragma unroll
            for (int ks = 0; ks < 4; ks++) {
                int pr = wid * 16 + (lane >> 2);
                int pc = ks * 8 + (lane & 3);
                unsigned a0 = __float_as_uint(Ps[pr][pc]);
                unsigned a1 = __float_as_uint(Ps[pr+8][pc]);
                unsigned a2 = __float_as_uint(Ps[pr][pc+4]);
                unsigned a3 = __float_as_uint(Ps[pr+8][pc+4]);
#pragma unroll
                for (int dt = 0; dt < 8; dt++) {
                    int kk = ks * 8 + (lane & 3);
                    int nn = dt * 8 + (lane >> 2);
                    unsigned b0 = __float_as_uint(Vs[kk][nn]);
                    unsigned b1 = __float_as_uint(Vs[kk+4][nn]);
                    mma8(oacc[dt], a0, a1, a2, a3, b0, b1);
                }
            }
        }
        __syncthreads();
    }

    // final row sums across quad, normalize, write
    l0 += __shfl_xor_sync(0xffffffff, l0, 1);
    l0 += __shfl_xor_sync(0xffffffff, l0, 2);
    l1 += __shfl_xor_sync(0xffffffff, l1, 1);
    l1 += __shfl_xor_sync(0xffffffff, l1, 2);
    float inv0 = 1.0f / l0;
    float inv1 = 1.0f / l1;

    float* obase = ctx + (size_t)(b * N_) * DOUT + h * DH_;
#pragma unroll
    for (int dt = 0; dt < 8; dt++) {
        int col = dt * 8 + 2 * (lane & 3);
        float2 v0 = make_float2(oacc[dt][0] * inv0, oacc[dt][1] * inv0);
        float2 v1 = make_float2(oacc[dt][2] * inv1, oacc[dt][3] * inv1);
        *(float2*)(obase + (size_t)r0 * DOUT + col)       = v0;
        *(float2*)(obase + (size_t)(r0 + 8) * DOUT + col) = v1;
    }
}

// ===================================================================
// Launch
// ===================================================================
extern "C" void kernel_launch(void* const* d_in, const int* in_sizes, int n_in,
                              void* d_out, int out_size)
{
    const float* x  = (const float*)d_in[0];
    const float* Wq = (const float*)d_in[1];
    const float* Wk = (const float*)d_in[2];
    const float* Wv = (const float*)d_in[3];
    const float* Wo = (const float*)d_in[4];
    const float* bo = (const float*)d_in[5];
    float* out = (float*)d_out;

    float *Q, *K, *V, *Ctx;
    cudaGetSymbolAddress((void**)&Q,   g_Q);
    cudaGetSymbolAddress((void**)&K,   g_K);
    cudaGetSymbolAddress((void**)&V,   g_V);
    cudaGetSymbolAddress((void**)&Ctx, g_ctx);

    gemm3t<<<dim3(DOUT / 128, M_ / 128), 256>>>(x, Wq, Q, nullptr, M_, DOUT, DIN);
    gemm3t<<<dim3(KVD  / 128, M_ / 128), 256>>>(x, Wk, K, nullptr, M_, KVD,  DIN);
    gemm3t<<<dim3(KVD  / 128, M_ / 128), 256>>>(x, Wv, V, nullptr, M_, KVD,  DIN);

    flash_mma<<<dim3(N_ / FBM, H_, B_), 128>>>(Q, K, V, Ctx);

    gemm3t<<<dim3(DIN / 128, M_ / 128), 256>>>(Ctx, Wo, out, bo, M_, DIN, DOUT);
}

// round 3
// speedup vs baseline: 3.0975x; 1.6666x over previous
#include <cuda_runtime.h>
#include <cuda_bf16.h>
#include <math.h>

// Problem constants
#define B_   2
#define N_   2048
#define DIN  2048
#define DOUT 2048
#define H_   32
#define KV_  8
#define DH_  64
#define M_   (B_ * N_)          // 4096
#define QKVW 3072               // fused Q|K|V output width

// -------- scratch (allocation-free rule: __device__ globals) --------
__device__ float          g_QKV[(size_t)M_ * QKVW];          // 50 MB fused proj out
__device__ __nv_bfloat16  g_xh[(size_t)M_ * DIN];
__device__ __nv_bfloat16  g_xl[(size_t)M_ * DIN];
__device__ __nv_bfloat16  g_Wqkv_h[(size_t)QKVW * DIN];      // transposed [n][k]
__device__ __nv_bfloat16  g_Wqkv_l[(size_t)QKVW * DIN];
__device__ __nv_bfloat16  g_Wo_h[(size_t)DIN * DOUT];        // transposed [n][k], k=DOUT
__device__ __nv_bfloat16  g_Wo_l[(size_t)DIN * DOUT];
__device__ __nv_bfloat16  g_ctxh[(size_t)M_ * DOUT];
__device__ __nv_bfloat16  g_ctxl[(size_t)M_ * DOUT];

// ---------------- helpers ----------------
__device__ __forceinline__ unsigned f2tf(float x) {
    unsigned r; asm("cvt.rna.tf32.f32 %0, %1;" : "=r"(r) : "f"(x)); return r;
}
__device__ __forceinline__ void bsplit2(float a, float b, unsigned& hi, unsigned& lo) {
    __nv_bfloat162 h = __floats2bfloat162_rn(a, b);
    float ra = a - __bfloat162float(h.x);
    float rb = b - __bfloat162float(h.y);
    __nv_bfloat162 l = __floats2bfloat162_rn(ra, rb);
    hi = *reinterpret_cast<unsigned*>(&h);
    lo = *reinterpret_cast<unsigned*>(&l);
}
// bf16 m16n8k16 mma
__device__ __forceinline__ void mma16(float c[4], const unsigned a[4], const unsigned b[2]) {
    asm volatile(
        "mma.sync.aligned.m16n8k16.row.col.f32.bf16.bf16.f32 "
        "{%0,%1,%2,%3}, {%4,%5,%6,%7}, {%8,%9}, {%0,%1,%2,%3};"
        : "+f"(c[0]), "+f"(c[1]), "+f"(c[2]), "+f"(c[3])
        : "r"(a[0]), "r"(a[1]), "r"(a[2]), "r"(a[3]), "r"(b[0]), "r"(b[1]));
}
// tf32 m16n8k8 mma (PV path)
__device__ __forceinline__ void mma8(float c[4], unsigned a0, unsigned a1, unsigned a2, unsigned a3,
                                     unsigned b0, unsigned b1) {
    asm volatile(
        "mma.sync.aligned.m16n8k8.row.col.f32.tf32.tf32.f32 "
        "{%0,%1,%2,%3}, {%4,%5,%6,%7}, {%8,%9}, {%0,%1,%2,%3};"
        : "+f"(c[0]), "+f"(c[1]), "+f"(c[2]), "+f"(c[3])
        : "r"(a0), "r"(a1), "r"(a2), "r"(a3), "r"(b0), "r"(b1));
}

// ===================================================================
// Conversion kernels (memory-bound, run once per launch)
// ===================================================================
__global__ __launch_bounds__(256)
void split_x_kernel(const float* __restrict__ src,
                    __nv_bfloat16* __restrict__ hi, __nv_bfloat16* __restrict__ lo)
{
    size_t i = (size_t)(blockIdx.x * 256 + threadIdx.x);   // float4 index
    float4 v = ((const float4*)src)[i];
    unsigned h0, l0, h1, l1;
    bsplit2(v.x, v.y, h0, l0);
    bsplit2(v.z, v.w, h1, l1);
    ((uint2*)hi)[i] = make_uint2(h0, h1);
    ((uint2*)lo)[i] = make_uint2(l0, l1);
}

// src [K][N] fp32 -> dst_(hi|lo)[row_off + n][k] bf16 (dst stride = K)
__global__ __launch_bounds__(256)
void tsplit_kernel(const float* __restrict__ src,
                   __nv_bfloat16* __restrict__ dh, __nv_bfloat16* __restrict__ dl,
                   int K, int N, int row_off)
{
    __shared__ float t[32][33];
    int n0 = blockIdx.x * 32, k0 = blockIdx.y * 32;
    int tx = threadIdx.x & 31, ty = threadIdx.x >> 5;   // 32 x 8
#pragma unroll
    for (int i = 0; i < 4; i++)
        t[ty + i * 8][tx] = src[(size_t)(k0 + ty + i * 8) * N + n0 + tx];
    __syncthreads();
#pragma unroll
    for (int i = 0; i < 4; i++) {
        int n = ty + i * 8;
        float v = t[tx][n];
        size_t idx = (size_t)(row_off + n0 + n) * K + k0 + tx;
        __nv_bfloat16 hv = __float2bfloat16_rn(v);
        __nv_bfloat16 lv = __float2bfloat16_rn(v - __bfloat162float(hv));
        dh[idx] = hv;
        dl[idx] = lv;
    }
}

// ===================================================================
// 3xBF16-split GEMM: C[M,Nc] = A[M,K] @ B^T  (B stored [Nc][K])
// block 128x128, KT=32, 8 warps (2x4), warp tile 64x32
// smem holds bf16 pairs as unsigned (k2 = k/2 index), stride 20 words
// ===================================================================
#define GKT 32
#define GST 20

__global__ __launch_bounds__(256)
void gemm_bf16(const __nv_bfloat16* __restrict__ Ahg, const __nv_bfloat16* __restrict__ Alg,
               const __nv_bfloat16* __restrict__ Bhg, const __nv_bfloat16* __restrict__ Blg,
               float* __restrict__ C, const float* __restrict__ bias,
               int M, int Nc, int K)
{
    __shared__ unsigned Ah[128][GST], Al[128][GST];
    __shared__ unsigned Bh[128][GST], Bl[128][GST];

    const int tid  = threadIdx.x;
    const int lane = tid & 31;
    const int wid  = tid >> 5;
    const int wr   = (wid >> 2) * 64;
    const int wc   = (wid & 3) * 32;
    const int brow = blockIdx.y * 128;
    const int bcol = blockIdx.x * 128;
    const int q    = lane & 3;
    const int l4   = lane >> 2;

    float acc[4][4][4];
#pragma unroll
    for (int i = 0; i < 4; i++)
#pragma unroll
        for (int j = 0; j < 4; j++)
#pragma unroll
            for (int e = 0; e < 4; e++) acc[i][j][e] = 0.0f;

    for (int k0 = 0; k0 < K; k0 += GKT) {
        // A tile: 128 rows x 32 k (16 uints) ; 512 uint4 -> 2/thread per buffer
#pragma unroll
        for (int p = 0; p < 2; p++) {
            int id = tid + p * 256;
            int r = id >> 2;
            int c2 = (id & 3) * 4;               // uint column
            size_t gi = (size_t)(brow + r) * K + k0 + c2 * 2;
            *(uint4*)&Ah[r][c2] = *(const uint4*)(Ahg + gi);
            *(uint4*)&Al[r][c2] = *(const uint4*)(Alg + gi);
            size_t gb = (size_t)(bcol + r) * K + k0 + c2 * 2;
            *(uint4*)&Bh[r][c2] = *(const uint4*)(Bhg + gb);
            *(uint4*)&Bl[r][c2] = *(const uint4*)(Blg + gb);
        }
        __syncthreads();

#pragma unroll
        for (int ks2 = 0; ks2 < 16; ks2 += 8) {      // two k16 steps
            unsigned ah[4][4], al[4][4], bh[4][2], bl[4][2];
#pragma unroll
            for (int mt = 0; mt < 4; mt++) {
                int r = wr + mt * 16 + l4;
                ah[mt][0] = Ah[r][ks2 + q];
                ah[mt][1] = Ah[r + 8][ks2 + q];
                ah[mt][2] = Ah[r][ks2 + q + 4];
                ah[mt][3] = Ah[r + 8][ks2 + q + 4];
                al[mt][0] = Al[r][ks2 + q];
                al[mt][1] = Al[r + 8][ks2 + q];
                al[mt][2] = Al[r][ks2 + q + 4];
                al[mt][3] = Al[r + 8][ks2 + q + 4];
            }
#pragma unroll
            for (int nt = 0; nt < 4; nt++) {
                int n = wc + nt * 8 + l4;
                bh[nt][0] = Bh[n][ks2 + q];
                bh[nt][1] = Bh[n][ks2 + q + 4];
                bl[nt][0] = Bl[n][ks2 + q];
                bl[nt][1] = Bl[n][ks2 + q + 4];
            }
#pragma unroll
            for (int mt = 0; mt < 4; mt++)
#pragma unroll
                for (int nt = 0; nt < 4; nt++) {
                    mma16(acc[mt][nt], ah[mt], bh[nt]);
                    mma16(acc[mt][nt], ah[mt], bl[nt]);
                    mma16(acc[mt][nt], al[mt], bh[nt]);
                }
        }
        __syncthreads();
    }

#pragma unroll
    for (int mt = 0; mt < 4; mt++) {
#pragma unroll
        for (int nt = 0; nt < 4; nt++) {
            int row = brow + wr + mt * 16 + l4;
            int col = bcol + wc + nt * 8 + 2 * q;
            float b0 = 0.f, b1 = 0.f;
            if (bias) { b0 = bias[col]; b1 = bias[col + 1]; }
            float2 v0 = make_float2(acc[mt][nt][0] + b0, acc[mt][nt][1] + b1);
            float2 v1 = make_float2(acc[mt][nt][2] + b0, acc[mt][nt][3] + b1);
            *(float2*)(C + (size_t)row * Nc + col)       = v0;
            *(float2*)(C + (size_t)(row + 8) * Nc + col) = v1;
        }
    }
}

// ===================================================================
// Flash attention. Block = 64 q rows of one (b, h). 4 warps x 16 rows.
// QK^T: 3xBF16-split (k16). PV: 1xTF32 (k8). Base-2 softmax.
// Writes ctx directly as split bf16.
// ===================================================================
#define FBM 64
#define FBN 32
#define KS2 36   // K smem stride in uints
#define VST 72
#define PST 36

__global__ __launch_bounds__(128)
void flash_mma(const float* __restrict__ QKV,
               __nv_bfloat16* __restrict__ ctxh, __nv_bfloat16* __restrict__ ctxl)
{
    __shared__ unsigned Kh[FBN][KS2], Kl[FBN][KS2];
    __shared__ float Vs[FBN][VST];
    __shared__ float Ps[FBM][PST];

    const int tid  = threadIdx.x;
    const int lane = tid & 31;
    const int wid  = tid >> 5;
    const int q    = lane & 3;
    const int l4   = lane >> 2;
    const int m0   = blockIdx.x * FBM;
    const int h    = blockIdx.y;
    const int b    = blockIdx.z;
    const int kv   = h >> 2;

    const int r0 = m0 + wid * 16 + l4;
    const float qscale = 0.125f * 1.44269504f;

    // Q fragments bf16 hi/lo: 4 k16 steps over DH=64
    unsigned qh[4][4], ql[4][4];
    {
        const float* qbase = QKV + (size_t)(b * N_) * QKVW + h * DH_;
#pragma unroll
        for (int ks = 0; ks < 4; ks++) {
            int c = ks * 16 + 2 * q;
#pragma unroll
            for (int half = 0; half < 2; half++) {
                int cc = c + half * 8;
                float2 v0 = *(const float2*)(qbase + (size_t)r0 * QKVW + cc);
                float2 v1 = *(const float2*)(qbase + (size_t)(r0 + 8) * QKVW + cc);
                bsplit2(v0.x * qscale, v0.y * qscale, qh[ks][half * 2],     ql[ks][half * 2]);
                bsplit2(v1.x * qscale, v1.y * qscale, qh[ks][half * 2 + 1], ql[ks][half * 2 + 1]);
            }
        }
    }

    float oacc[8][4];
#pragma unroll
    for (int d = 0; d < 8; d++)
#pragma unroll
        for (int e = 0; e < 4; e++) oacc[d][e] = 0.0f;
    float mcur0 = -1e30f, mcur1 = -1e30f, l0 = 0.0f, l1 = 0.0f;

    const int rowmax = m0 + wid * 16 + 15;
    const int nend = m0 + FBM;

    const float* kb = QKV + (size_t)(b * N_) * QKVW + 2048 + kv * DH_;
    const float* vb = QKV + (size_t)(b * N_) * QKVW + 2560 + kv * DH_;

    for (int n0 = 0; n0 < nend; n0 += FBN) {
#pragma unroll
        for (int p = 0; p < 4; p++) {
            int id = tid + p * 128;
            int r = id >> 4;
            int c = (id & 15) * 4;
            float4 kvv = *(const float4*)(kb + (size_t)(n0 + r) * QKVW + c);
            bsplit2(kvv.x, kvv.y, Kh[r][c / 2],     Kl[r][c / 2]);
            bsplit2(kvv.z, kvv.w, Kh[r][c / 2 + 1], Kl[r][c / 2 + 1]);
            float4 vv = *(const float4*)(vb + (size_t)(n0 + r) * QKVW + c);
            Vs[r][c + 0] = __uint_as_float(f2tf(vv.x));
            Vs[r][c + 1] = __uint_as_float(f2tf(vv.y));
            Vs[r][c + 2] = __uint_as_float(f2tf(vv.z));
            Vs[r][c + 3] = __uint_as_float(f2tf(vv.w));
        }
        __syncthreads();

        if (n0 <= rowmax) {
            // ---- S = Q K^T : 3xBF16, 4 k16 steps ----
            float s[4][4];
#pragma unroll
            for (int nt = 0; nt < 4; nt++)
#pragma unroll
                for (int e = 0; e < 4; e++) s[nt][e] = 0.0f;

#pragma unroll
            for (int ks = 0; ks < 4; ks++) {
                unsigned bh[4][2], bl[4][2];
#pragma unroll
                for (int nt = 0; nt < 4; nt++) {
                    int n = nt * 8 + l4;
                    bh[nt][0] = Kh[n][ks * 8 + q];
                    bh[nt][1] = Kh[n][ks * 8 + q + 4];
                    bl[nt][0] = Kl[n][ks * 8 + q];
                    bl[nt][1] = Kl[n][ks * 8 + q + 4];
                }
#pragma unroll
                for (int nt = 0; nt < 4; nt++) {
                    mma16(s[nt], qh[ks], bh[nt]);
                    mma16(s[nt], qh[ks], bl[nt]);
                    mma16(s[nt], ql[ks], bh[nt]);
                }
            }

            // ---- causal mask + row max ----
            float mt0 = -1e30f, mt1 = -1e30f;
#pragma unroll
            for (int nt = 0; nt < 4; nt++) {
#pragma unroll
                for (int e = 0; e < 2; e++) {
                    int col = n0 + nt * 8 + 2 * q + e;
                    if (col > r0)     s[nt][e]     = -1e30f;
                    if (col > r0 + 8) s[nt][2 + e] = -1e30f;
                    mt0 = fmaxf(mt0, s[nt][e]);
                    mt1 = fmaxf(mt1, s[nt][2 + e]);
                }
            }
            mt0 = fmaxf(mt0, __shfl_xor_sync(0xffffffff, mt0, 1));
            mt0 = fmaxf(mt0, __shfl_xor_sync(0xffffffff, mt0, 2));
            mt1 = fmaxf(mt1, __shfl_xor_sync(0xffffffff, mt1, 1));
            mt1 = fmaxf(mt1, __shfl_xor_sync(0xffffffff, mt1, 2));

            float mn0 = fmaxf(mcur0, mt0);
            float mn1 = fmaxf(mcur1, mt1);
            float cr0 = exp2f(mcur0 - mn0);
            float cr1 = exp2f(mcur1 - mn1);
            l0 *= cr0; l1 *= cr1;
#pragma unroll
            for (int d = 0; d < 8; d++) {
                oacc[d][0] *= cr0; oacc[d][1] *= cr0;
                oacc[d][2] *= cr1; oacc[d][3] *= cr1;
            }

            int prow = wid * 16 + l4;
#pragma unroll
            for (int nt = 0; nt < 4; nt++) {
                int pc = nt * 8 + 2 * q;
                float p00 = exp2f(s[nt][0] - mn0);
                float p01 = exp2f(s[nt][1] - mn0);
                float p10 = exp2f(s[nt][2] - mn1);
                float p11 = exp2f(s[nt][3] - mn1);
                l0 += p00 + p01;
                l1 += p10 + p11;
                Ps[prow][pc]         = __uint_as_float(f2tf(p00));
                Ps[prow][pc + 1]     = __uint_as_float(f2tf(p01));
                Ps[prow + 8][pc]     = __uint_as_float(f2tf(p10));
                Ps[prow + 8][pc + 1] = __uint_as_float(f2tf(p11));
            }
            mcur0 = mn0; mcur1 = mn1;
            __syncwarp();

            // ---- O += P V (1xTF32), 4 k8 steps ----
#pragma unroll
            for (int ks = 0; ks < 4; ks++) {
                int pr = wid * 16 + l4;
                int pc = ks * 8 + q;
                unsigned a0 = __float_as_uint(Ps[pr][pc]);
                unsigned a1 = __float_as_uint(Ps[pr + 8][pc]);
                unsigned a2 = __float_as_uint(Ps[pr][pc + 4]);
                unsigned a3 = __float_as_uint(Ps[pr + 8][pc + 4]);
#pragma unroll
                for (int dt = 0; dt < 8; dt++) {
                    int kk = ks * 8 + q;
                    int nn = dt * 8 + l4;
                    unsigned b0 = __float_as_uint(Vs[kk][nn]);
                    unsigned b1 = __float_as_uint(Vs[kk + 4][nn]);
                    mma8(oacc[dt], a0, a1, a2, a3, b0, b1);
                }
            }
        }
        __syncthreads();
    }

    l0 += __shfl_xor_sync(0xffffffff, l0, 1);
    l0 += __shfl_xor_sync(0xffffffff, l0, 2);
    l1 += __shfl_xor_sync(0xffffffff, l1, 1);
    l1 += __shfl_xor_sync(0xffffffff, l1, 2);
    float inv0 = 1.0f / l0;
    float inv1 = 1.0f / l1;

    // write ctx as split bf16 (feeds out-proj GEMM directly)
    size_t obase = (size_t)(b * N_) * DOUT + h * DH_;
#pragma unroll
    for (int dt = 0; dt < 8; dt++) {
        int col = dt * 8 + 2 * q;
        unsigned hu, lu;
        bsplit2(oacc[dt][0] * inv0, oacc[dt][1] * inv0, hu, lu);
        *(unsigned*)(ctxh + obase + (size_t)r0 * DOUT + col) = hu;
        *(unsigned*)(ctxl + obase + (size_t)r0 * DOUT + col) = lu;
        bsplit2(oacc[dt][2] * inv1, oacc[dt][3] * inv1, hu, lu);
        *(unsigned*)(ctxh + obase + (size_t)(r0 + 8) * DOUT + col) = hu;
        *(unsigned*)(ctxl + obase + (size_t)(r0 + 8) * DOUT + col) = lu;
    }
}

// ===================================================================
// Launch
// ===================================================================
extern "C" void kernel_launch(void* const* d_in, const int* in_sizes, int n_in,
                              void* d_out, int out_size)
{
    const float* x  = (const float*)d_in[0];
    const float* Wq = (const float*)d_in[1];
    const float* Wk = (const float*)d_in[2];
    const float* Wv = (const float*)d_in[3];
    const float* Wo = (const float*)d_in[4];
    const float* bo = (const float*)d_in[5];
    float* out = (float*)d_out;

    float *QKV;
    __nv_bfloat16 *xh, *xl, *Wqkv_h, *Wqkv_l, *Wo_h, *Wo_l, *ctxh, *ctxl;
    cudaGetSymbolAddress((void**)&QKV,    g_QKV);
    cudaGetSymbolAddress((void**)&xh,     g_xh);
    cudaGetSymbolAddress((void**)&xl,     g_xl);
    cudaGetSymbolAddress((void**)&Wqkv_h, g_Wqkv_h);
    cudaGetSymbolAddress((void**)&Wqkv_l, g_Wqkv_l);
    cudaGetSymbolAddress((void**)&Wo_h,   g_Wo_h);
    cudaGetSymbolAddress((void**)&Wo_l,   g_Wo_l);
    cudaGetSymbolAddress((void**)&ctxh,   g_ctxh);
    cudaGetSymbolAddress((void**)&ctxl,   g_ctxl);

    // conversions
    split_x_kernel<<<(int)((size_t)M_ * DIN / 4 / 256), 256>>>(x, xh, xl);
    tsplit_kernel<<<dim3(2048 / 32, DIN / 32), 256>>>(Wq, Wqkv_h, Wqkv_l, DIN, 2048, 0);
    tsplit_kernel<<<dim3(512 / 32,  DIN / 32), 256>>>(Wk, Wqkv_h, Wqkv_l, DIN, 512, 2048);
    tsplit_kernel<<<dim3(512 / 32,  DIN / 32), 256>>>(Wv, Wqkv_h, Wqkv_l, DIN, 512, 2560);
    tsplit_kernel<<<dim3(DIN / 32,  DOUT / 32), 256>>>(Wo, Wo_h, Wo_l, DOUT, DIN, 0);

    // fused QKV projection: [4096,2048] @ [2048,3072] -> [4096,3072]
    gemm_bf16<<<dim3(QKVW / 128, M_ / 128), 256>>>(xh, xl, Wqkv_h, Wqkv_l, QKV, nullptr,
                                                   M_, QKVW, DIN);

    // attention
    flash_mma<<<dim3(N_ / FBM, H_, B_), 128>>>(QKV, ctxh, ctxl);

    // output projection + bias: [4096,2048] @ [2048,2048] -> out
    gemm_bf16<<<dim3(DIN / 128, M_ / 128), 256>>>(ctxh, ctxl, Wo_h, Wo_l, out, bo,
                                                  M_, DIN, DOUT);
}

// round 7
// speedup vs baseline: 4.0263x; 1.2999x over previous
#include <cuda_runtime.h>
#include <cuda_bf16.h>
#include <cstdint>
#include <math.h>

// Problem constants
#define B_   2
#define N_   2048
#define DIN  2048
#define DOUT 2048
#define H_   32
#define KV_  8
#define DH_  64
#define M_   (B_ * N_)          // 4096
#define QKVW 3072               // fused Q|K|V output width

// -------- scratch (allocation-free rule: __device__ globals) --------
__device__ float          g_QKV[(size_t)M_ * QKVW];
__device__ __nv_bfloat16  g_xh[(size_t)M_ * DIN];
__device__ __nv_bfloat16  g_xl[(size_t)M_ * DIN];
__device__ __nv_bfloat16  g_Wqkv_h[(size_t)QKVW * DIN];      // transposed [n][k]
__device__ __nv_bfloat16  g_Wqkv_l[(size_t)QKVW * DIN];
__device__ __nv_bfloat16  g_Wo_h[(size_t)DIN * DOUT];        // transposed [n][k]
__device__ __nv_bfloat16  g_Wo_l[(size_t)DIN * DOUT];
__device__ __nv_bfloat16  g_ctxh[(size_t)M_ * DOUT];
__device__ __nv_bfloat16  g_ctxl[(size_t)M_ * DOUT];

// ---------------- helpers ----------------
__device__ __forceinline__ unsigned f2tf(float x) {
    unsigned r; asm("cvt.rna.tf32.f32 %0, %1;" : "=r"(r) : "f"(x)); return r;
}
__device__ __forceinline__ void bsplit2(float a, float b, unsigned& hi, unsigned& lo) {
    __nv_bfloat162 h = __floats2bfloat162_rn(a, b);
    float ra = a - __bfloat162float(h.x);
    float rb = b - __bfloat162float(h.y);
    __nv_bfloat162 l = __floats2bfloat162_rn(ra, rb);
    hi = *reinterpret_cast<unsigned*>(&h);
    lo = *reinterpret_cast<unsigned*>(&l);
}
__device__ __forceinline__ void mma16(float c[4], const unsigned a[4], const unsigned b[2]) {
    asm volatile(
        "mma.sync.aligned.m16n8k16.row.col.f32.bf16.bf16.f32 "
        "{%0,%1,%2,%3}, {%4,%5,%6,%7}, {%8,%9}, {%0,%1,%2,%3};"
        : "+f"(c[0]), "+f"(c[1]), "+f"(c[2]), "+f"(c[3])
        : "r"(a[0]), "r"(a[1]), "r"(a[2]), "r"(a[3]), "r"(b[0]), "r"(b[1]));
}
__device__ __forceinline__ void mma8(float c[4], unsigned a0, unsigned a1, unsigned a2, unsigned a3,
                                     unsigned b0, unsigned b1) {
    asm volatile(
        "mma.sync.aligned.m16n8k8.row.col.f32.tf32.tf32.f32 "
        "{%0,%1,%2,%3}, {%4,%5,%6,%7}, {%8,%9}, {%0,%1,%2,%3};"
        : "+f"(c[0]), "+f"(c[1]), "+f"(c[2]), "+f"(c[3])
        : "r"(a0), "r"(a1), "r"(a2), "r"(a3), "r"(b0), "r"(b1));
}
__device__ __forceinline__ unsigned smem_u32(const void* p) {
    unsigned a;
    asm("{ .reg .u64 t; cvta.to.shared.u64 t, %1; cvt.u32.u64 %0, t; }" : "=r"(a) : "l"(p));
    return a;
}
__device__ __forceinline__ void ldsm4(unsigned& r0, unsigned& r1, unsigned& r2, unsigned& r3,
                                      unsigned addr) {
    asm volatile("ldmatrix.sync.aligned.m8n8.x4.shared.b16 {%0,%1,%2,%3}, [%4];"
                 : "=r"(r0), "=r"(r1), "=r"(r2), "=r"(r3) : "r"(addr));
}
__device__ __forceinline__ void cpa16(unsigned saddr, const void* g) {
    asm volatile("cp.async.cg.shared.global [%0], [%1], 16;" :: "r"(saddr), "l"(g));
}

// ===================================================================
// Conversion kernels
// ===================================================================
__global__ __launch_bounds__(256)
void split_x_kernel(const float* __restrict__ src,
                    __nv_bfloat16* __restrict__ hi, __nv_bfloat16* __restrict__ lo)
{
    size_t i = (size_t)(blockIdx.x * 256 + threadIdx.x);
    float4 v = ((const float4*)src)[i];
    unsigned h0, l0, h1, l1;
    bsplit2(v.x, v.y, h0, l0);
    bsplit2(v.z, v.w, h1, l1);
    ((uint2*)hi)[i] = make_uint2(h0, h1);
    ((uint2*)lo)[i] = make_uint2(l0, l1);
}

__global__ __launch_bounds__(256)
void tsplit_kernel(const float* __restrict__ src,
                   __nv_bfloat16* __restrict__ dh, __nv_bfloat16* __restrict__ dl,
                   int K, int N, int row_off)
{
    __shared__ float t[32][33];
    int n0 = blockIdx.x * 32, k0 = blockIdx.y * 32;
    int tx = threadIdx.x & 31, ty = threadIdx.x >> 5;
#pragma unroll
    for (int i = 0; i < 4; i++)
        t[ty + i * 8][tx] = src[(size_t)(k0 + ty + i * 8) * N + n0 + tx];
    __syncthreads();
#pragma unroll
    for (int i = 0; i < 4; i++) {
        int n = ty + i * 8;
        float v = t[tx][n];
        size_t idx = (size_t)(row_off + n0 + n) * K + k0 + tx;
        __nv_bfloat16 hv = __float2bfloat16_rn(v);
        __nv_bfloat16 lv = __float2bfloat16_rn(v - __bfloat162float(hv));
        dh[idx] = hv;
        dl[idx] = lv;
    }
}

// ===================================================================
// 3xBF16-split GEMM with cp.async double buffering + ldmatrix.
// C[M,Nc] = A[M,K] @ B^T (B stored [Nc][K]). block 128x128, KT=32,
// 8 warps (2x4), warp tile 64x32.
// smem per stage: 4 buffers (Ah,Al,Bh,Bl) of 128 rows x 16 words (+4 pad).
// ===================================================================
#define GST 20                        // words per row (16 data + 4 pad)
#define BUF_WORDS (128 * GST)         // 2560 words = 10240 B
#define BUFB (BUF_WORDS * 4)          // bytes per buffer
#define STAGEB (4 * BUFB)             // 40960 B per stage
#define GEMM_SMEMB (2 * STAGEB)       // 81920 B

__global__ __launch_bounds__(256)
void gemm_bf16(const __nv_bfloat16* __restrict__ Ahg, const __nv_bfloat16* __restrict__ Alg,
               const __nv_bfloat16* __restrict__ Bhg, const __nv_bfloat16* __restrict__ Blg,
               float* __restrict__ C, const float* __restrict__ bias,
               int Nc, int K)
{
    extern __shared__ unsigned smw[];
    const unsigned sb = smem_u32(smw);

    const int tid  = threadIdx.x;
    const int lane = tid & 31;
    const int wid  = tid >> 5;
    const int wr   = (wid >> 2) * 64;
    const int wc   = (wid & 3) * 32;
    const int brow = blockIdx.y * 128;
    const int bcol = blockIdx.x * 128;
    const int q    = lane & 3;
    const int l4   = lane >> 2;
    const int Kw   = K >> 1;                 // words (2 bf16) per row
    const int sub  = lane >> 3;              // ldmatrix sub-matrix id
    const int r8   = lane & 7;

    const unsigned* Ahw = (const unsigned*)Ahg;
    const unsigned* Alw = (const unsigned*)Alg;
    const unsigned* Bhw = (const unsigned*)Bhg;
    const unsigned* Blw = (const unsigned*)Blg;

    // per-thread load coords (2 x uint4 per buffer)
    const int r_a  = tid >> 1;               // for p-loop variant below
    (void)r_a;

    float acc[4][4][4];
#pragma unroll
    for (int i = 0; i < 4; i++)
#pragma unroll
        for (int j = 0; j < 4; j++)
#pragma unroll
            for (int e = 0; e < 4; e++) acc[i][j][e] = 0.0f;

    const int nst = K / 32;                  // stages of 32 k (16 words)

    // ---- stage issue: 8 cp.async (16B) per thread ----
    auto issue = [&](int stage, int kw0) {
        unsigned sd = sb + stage * STAGEB;
#pragma unroll
        for (int p = 0; p < 2; p++) {
            int id = tid + p * 256;
            int r  = id >> 2;
            int c4 = (id & 3) * 4;
            size_t gA = (size_t)(brow + r) * Kw + kw0 + c4;
            size_t gB = (size_t)(bcol + r) * Kw + kw0 + c4;
            unsigned o = (unsigned)(r * GST + c4) * 4;
            cpa16(sd + 0 * BUFB + o, Ahw + gA);
            cpa16(sd + 1 * BUFB + o, Alw + gA);
            cpa16(sd + 2 * BUFB + o, Bhw + gB);
            cpa16(sd + 3 * BUFB + o, Blw + gB);
        }
        asm volatile("cp.async.commit_group;");
    };

    issue(0, 0);

    for (int i = 0; i < nst; i++) {
        if (i + 1 < nst) {
            issue((i + 1) & 1, (i + 1) * 16);
            asm volatile("cp.async.wait_group 1;");
        } else {
            asm volatile("cp.async.wait_group 0;");
        }
        __syncthreads();

        const unsigned sd = sb + (i & 1) * STAGEB;
        const unsigned sAh = sd, sAl = sd + BUFB, sBh = sd + 2 * BUFB, sBl = sd + 3 * BUFB;

#pragma unroll
        for (int ks2 = 0; ks2 < 16; ks2 += 8) {      // two k16 steps
            // ---- B fragments via ldmatrix x4 (2 nt per call) ----
            unsigned bh[4][2], bl[4][2];
#pragma unroll
            for (int pr = 0; pr < 4; pr += 2) {
                int nrow = wc + (pr + (sub >> 1)) * 8 + r8;
                int colw = ks2 + (sub & 1) * 4;
                unsigned off = (unsigned)(nrow * GST + colw) * 4;
                ldsm4(bh[pr][0], bh[pr][1], bh[pr + 1][0], bh[pr + 1][1], sBh + off);
                ldsm4(bl[pr][0], bl[pr][1], bl[pr + 1][0], bl[pr + 1][1], sBl + off);
            }
            // ---- A fragments + MMAs per mt ----
#pragma unroll
            for (int mt = 0; mt < 4; mt++) {
                int arow = wr + mt * 16 + (sub & 1) * 8 + r8;
                int colw = ks2 + (sub >> 1) * 4;
                unsigned off = (unsigned)(arow * GST + colw) * 4;
                unsigned ah[4], al[4];
                ldsm4(ah[0], ah[1], ah[2], ah[3], sAh + off);
                ldsm4(al[0], al[1], al[2], al[3], sAl + off);
#pragma unroll
                for (int nt = 0; nt < 4; nt++) {
                    mma16(acc[mt][nt], ah, bh[nt]);
                    mma16(acc[mt][nt], ah, bl[nt]);
                    mma16(acc[mt][nt], al, bh[nt]);
                }
            }
        }
        __syncthreads();
    }

    // epilogue
#pragma unroll
    for (int mt = 0; mt < 4; mt++) {
#pragma unroll
        for (int nt = 0; nt < 4; nt++) {
            int row = brow + wr + mt * 16 + l4;
            int col = bcol + wc + nt * 8 + 2 * q;
            float b0 = 0.f, b1 = 0.f;
            if (bias) { b0 = bias[col]; b1 = bias[col + 1]; }
            float2 v0 = make_float2(acc[mt][nt][0] + b0, acc[mt][nt][1] + b1);
            float2 v1 = make_float2(acc[mt][nt][2] + b0, acc[mt][nt][3] + b1);
            *(float2*)(C + (size_t)row * Nc + col)       = v0;
            *(float2*)(C + (size_t)(row + 8) * Nc + col) = v1;
        }
    }
}

// ===================================================================
// Flash attention (unchanged from R3 — known passing).
// ===================================================================
#define FBM 64
#define FBN 32
#define KS2 36
#define VST 72
#define PST 36

__global__ __launch_bounds__(128)
void flash_mma(const float* __restrict__ QKV,
               __nv_bfloat16* __restrict__ ctxh, __nv_bfloat16* __restrict__ ctxl)
{
    __shared__ unsigned Kh[FBN][KS2], Kl[FBN][KS2];
    __shared__ float Vs[FBN][VST];
    __shared__ float Ps[FBM][PST];

    const int tid  = threadIdx.x;
    const int lane = tid & 31;
    const int wid  = tid >> 5;
    const int q    = lane & 3;
    const int l4   = lane >> 2;
    const int m0   = blockIdx.x * FBM;
    const int h    = blockIdx.y;
    const int b    = blockIdx.z;
    const int kv   = h >> 2;

    const int r0 = m0 + wid * 16 + l4;
    const float qscale = 0.125f * 1.44269504f;

    unsigned qh[4][4], ql[4][4];
    {
        const float* qbase = QKV + (size_t)(b * N_) * QKVW + h * DH_;
#pragma unroll
        for (int ks = 0; ks < 4; ks++) {
            int c = ks * 16 + 2 * q;
#pragma unroll
            for (int half = 0; half < 2; half++) {
                int cc = c + half * 8;
                float2 v0 = *(const float2*)(qbase + (size_t)r0 * QKVW + cc);
                float2 v1 = *(const float2*)(qbase + (size_t)(r0 + 8) * QKVW + cc);
                bsplit2(v0.x * qscale, v0.y * qscale, qh[ks][half * 2],     ql[ks][half * 2]);
                bsplit2(v1.x * qscale, v1.y * qscale, qh[ks][half * 2 + 1], ql[ks][half * 2 + 1]);
            }
        }
    }

    float oacc[8][4];
#pragma unroll
    for (int d = 0; d < 8; d++)
#pragma unroll
        for (int e = 0; e < 4; e++) oacc[d][e] = 0.0f;
    float mcur0 = -1e30f, mcur1 = -1e30f, l0 = 0.0f, l1 = 0.0f;

    const int rowmax = m0 + wid * 16 + 15;
    const int nend = m0 + FBM;

    const float* kb = QKV + (size_t)(b * N_) * QKVW + 2048 + kv * DH_;
    const float* vb = QKV + (size_t)(b * N_) * QKVW + 2560 + kv * DH_;

    for (int n0 = 0; n0 < nend; n0 += FBN) {
#pragma unroll
        for (int p = 0; p < 4; p++) {
            int id = tid + p * 128;
            int r = id >> 4;
            int c = (id & 15) * 4;
            float4 kvv = *(const float4*)(kb + (size_t)(n0 + r) * QKVW + c);
            bsplit2(kvv.x, kvv.y, Kh[r][c / 2],     Kl[r][c / 2]);
            bsplit2(kvv.z, kvv.w, Kh[r][c / 2 + 1], Kl[r][c / 2 + 1]);
            float4 vv = *(const float4*)(vb + (size_t)(n0 + r) * QKVW + c);
            Vs[r][c + 0] = __uint_as_float(f2tf(vv.x));
            Vs[r][c + 1] = __uint_as_float(f2tf(vv.y));
            Vs[r][c + 2] = __uint_as_float(f2tf(vv.z));
            Vs[r][c + 3] = __uint_as_float(f2tf(vv.w));
        }
        __syncthreads();

        if (n0 <= rowmax) {
            float s[4][4];
#pragma unroll
            for (int nt = 0; nt < 4; nt++)
#pragma unroll
                for (int e = 0; e < 4; e++) s[nt][e] = 0.0f;

#pragma unroll
            for (int ks = 0; ks < 4; ks++) {
                unsigned bh[4][2], bl[4][2];
#pragma unroll
                for (int nt = 0; nt < 4; nt++) {
                    int n = nt * 8 + l4;
                    bh[nt][0] = Kh[n][ks * 8 + q];
                    bh[nt][1] = Kh[n][ks * 8 + q + 4];
                    bl[nt][0] = Kl[n][ks * 8 + q];
                    bl[nt][1] = Kl[n][ks * 8 + q + 4];
                }
#pragma unroll
                for (int nt = 0; nt < 4; nt++) {
                    mma16(s[nt], qh[ks], bh[nt]);
                    mma16(s[nt], qh[ks], bl[nt]);
                    mma16(s[nt], ql[ks], bh[nt]);
                }
            }

            float mt0 = -1e30f, mt1 = -1e30f;
#pragma unroll
            for (int nt = 0; nt < 4; nt++) {
#pragma unroll
                for (int e = 0; e < 2; e++) {
                    int col = n0 + nt * 8 + 2 * q + e;
                    if (col > r0)     s[nt][e]     = -1e30f;
                    if (col > r0 + 8) s[nt][2 + e] = -1e30f;
                    mt0 = fmaxf(mt0, s[nt][e]);
                    mt1 = fmaxf(mt1, s[nt][2 + e]);
                }
            }
            mt0 = fmaxf(mt0, __shfl_xor_sync(0xffffffff, mt0, 1));
            mt0 = fmaxf(mt0, __shfl_xor_sync(0xffffffff, mt0, 2));
            mt1 = fmaxf(mt1, __shfl_xor_sync(0xffffffff, mt1, 1));
            mt1 = fmaxf(mt1, __shfl_xor_sync(0xffffffff, mt1, 2));

            float mn0 = fmaxf(mcur0, mt0);
            float mn1 = fmaxf(mcur1, mt1);
            float cr0 = exp2f(mcur0 - mn0);
            float cr1 = exp2f(mcur1 - mn1);
            l0 *= cr0; l1 *= cr1;
#pragma unroll
            for (int d = 0; d < 8; d++) {
                oacc[d][0] *= cr0; oacc[d][1] *= cr0;
                oacc[d][2] *= cr1; oacc[d][3] *= cr1;
            }

            int prow = wid * 16 + l4;
#pragma unroll
            for (int nt = 0; nt < 4; nt++) {
                int pc = nt * 8 + 2 * q;
                float p00 = exp2f(s[nt][0] - mn0);
                float p01 = exp2f(s[nt][1] - mn0);
                float p10 = exp2f(s[nt][2] - mn1);
                float p11 = exp2f(s[nt][3] - mn1);
                l0 += p00 + p01;
                l1 += p10 + p11;
                Ps[prow][pc]         = __uint_as_float(f2tf(p00));
                Ps[prow][pc + 1]     = __uint_as_float(f2tf(p01));
                Ps[prow + 8][pc]     = __uint_as_float(f2tf(p10));
                Ps[prow + 8][pc + 1] = __uint_as_float(f2tf(p11));
            }
            mcur0 = mn0; mcur1 = mn1;
            __syncwarp();

#pragma unroll
            for (int ks = 0; ks < 4; ks++) {
                int pr = wid * 16 + l4;
                int pc = ks * 8 + q;
                unsigned a0 = __float_as_uint(Ps[pr][pc]);
                unsigned a1 = __float_as_uint(Ps[pr + 8][pc]);
                unsigned a2 = __float_as_uint(Ps[pr][pc + 4]);
                unsigned a3 = __float_as_uint(Ps[pr + 8][pc + 4]);
#pragma unroll
                for (int dt = 0; dt < 8; dt++) {
                    int kk = ks * 8 + q;
                    int nn = dt * 8 + l4;
                    unsigned b0 = __float_as_uint(Vs[kk][nn]);
                    unsigned b1 = __float_as_uint(Vs[kk + 4][nn]);
                    mma8(oacc[dt], a0, a1, a2, a3, b0, b1);
                }
            }
        }
        __syncthreads();
    }

    l0 += __shfl_xor_sync(0xffffffff, l0, 1);
    l0 += __shfl_xor_sync(0xffffffff, l0, 2);
    l1 += __shfl_xor_sync(0xffffffff, l1, 1);
    l1 += __shfl_xor_sync(0xffffffff, l1, 2);
    float inv0 = 1.0f / l0;
    float inv1 = 1.0f / l1;

    size_t obase = (size_t)(b * N_) * DOUT + h * DH_;
#pragma unroll
    for (int dt = 0; dt < 8; dt++) {
        int col = dt * 8 + 2 * q;
        unsigned hu, lu;
        bsplit2(oacc[dt][0] * inv0, oacc[dt][1] * inv0, hu, lu);
        *(unsigned*)(ctxh + obase + (size_t)r0 * DOUT + col) = hu;
        *(unsigned*)(ctxl + obase + (size_t)r0 * DOUT + col) = lu;
        bsplit2(oacc[dt][2] * inv1, oacc[dt][3] * inv1, hu, lu);
        *(unsigned*)(ctxh + obase + (size_t)(r0 + 8) * DOUT + col) = hu;
        *(unsigned*)(ctxl + obase + (size_t)(r0 + 8) * DOUT + col) = lu;
    }
}

// ===================================================================
// Launch
// ===================================================================
extern "C" void kernel_launch(void* const* d_in, const int* in_sizes, int n_in,
                              void* d_out, int out_size)
{
    const float* x  = (const float*)d_in[0];
    const float* Wq = (const float*)d_in[1];
    const float* Wk = (const float*)d_in[2];
    const float* Wv = (const float*)d_in[3];
    const float* Wo = (const float*)d_in[4];
    const float* bo = (const float*)d_in[5];
    float* out = (float*)d_out;

    float *QKV;
    __nv_bfloat16 *xh, *xl, *Wqkv_h, *Wqkv_l, *Wo_h, *Wo_l, *ctxh, *ctxl;
    cudaGetSymbolAddress((void**)&QKV,    g_QKV);
    cudaGetSymbolAddress((void**)&xh,     g_xh);
    cudaGetSymbolAddress((void**)&xl,     g_xl);
    cudaGetSymbolAddress((void**)&Wqkv_h, g_Wqkv_h);
    cudaGetSymbolAddress((void**)&Wqkv_l, g_Wqkv_l);
    cudaGetSymbolAddress((void**)&Wo_h,   g_Wo_h);
    cudaGetSymbolAddress((void**)&Wo_l,   g_Wo_l);
    cudaGetSymbolAddress((void**)&ctxh,   g_ctxh);
    cudaGetSymbolAddress((void**)&ctxl,   g_ctxl);

    cudaFuncSetAttribute(gemm_bf16, cudaFuncAttributeMaxDynamicSharedMemorySize,
                         GEMM_SMEMB);

    // conversions
    split_x_kernel<<<(int)((size_t)M_ * DIN / 4 / 256), 256>>>(x, xh, xl);
    tsplit_kernel<<<dim3(2048 / 32, DIN / 32), 256>>>(Wq, Wqkv_h, Wqkv_l, DIN, 2048, 0);
    tsplit_kernel<<<dim3(512 / 32,  DIN / 32), 256>>>(Wk, Wqkv_h, Wqkv_l, DIN, 512, 2048);
    tsplit_kernel<<<dim3(512 / 32,  DIN / 32), 256>>>(Wv, Wqkv_h, Wqkv_l, DIN, 512, 2560);
    tsplit_kernel<<<dim3(DIN / 32,  DOUT / 32), 256>>>(Wo, Wo_h, Wo_l, DOUT, DIN, 0);

    // fused QKV projection: [4096,2048] @ [2048,3072]^T-stored -> [4096,3072]
    gemm_bf16<<<dim3(QKVW / 128, M_ / 128), 256, GEMM_SMEMB>>>(
        xh, xl, Wqkv_h, Wqkv_l, QKV, nullptr, QKVW, DIN);

    // attention
    flash_mma<<<dim3(N_ / FBM, H_, B_), 128>>>(QKV, ctxh, ctxl);

    // output projection + bias
    gemm_bf16<<<dim3(DIN / 128, M_ / 128), 256, GEMM_SMEMB>>>(
        ctxh, ctxl, Wo_h, Wo_l, out, bo, DIN, DOUT);
}

// round 8
// speedup vs baseline: 8.7835x; 2.1815x over previous
#include <cuda_runtime.h>
#include <cuda_bf16.h>
#include <cuda_fp16.h>
#include <cstdint>
#include <math.h>

// Problem constants
#define B_   2
#define N_   2048
#define DIN  2048
#define DOUT 2048
#define H_   32
#define KV_  8
#define DH_  64
#define M_   (B_ * N_)          // 4096
#define QKVW 3072               // fused Q|K|V output width

// -------- scratch (allocation-free rule: __device__ globals) --------
__device__ float  g_QKV[(size_t)M_ * QKVW];                       // fp32 proj out
__device__ __align__(16) __half g_x16[(size_t)M_ * DIN];          // A for QKV gemm
__device__ __align__(16) __half g_Wqkv16[(size_t)QKVW * DIN];     // [n][k]
__device__ __align__(16) __half g_Wo16[(size_t)DIN * DOUT];       // [n][k]
__device__ __align__(16) __half g_Q16[(size_t)M_ * DOUT];         // qscale folded
__device__ __align__(16) __half g_K16[(size_t)M_ * 512];          // [m][kv*64+d]
__device__ __align__(16) __half g_Vt[(size_t)(B_ * KV_ * DH_) * N_]; // [(b,kv,d)][n]
__device__ __align__(16) __half g_c16[(size_t)M_ * DOUT];         // ctx fp16

// ---------------- helpers ----------------
__device__ __forceinline__ unsigned h2u(float a, float b) {
    __half2 h = __floats2half2_rn(a, b);
    return *reinterpret_cast<unsigned*>(&h);
}
__device__ __forceinline__ void mma16f(float c[4], const unsigned a[4], const unsigned b[2]) {
    asm volatile(
        "mma.sync.aligned.m16n8k16.row.col.f32.f16.f16.f32 "
        "{%0,%1,%2,%3}, {%4,%5,%6,%7}, {%8,%9}, {%0,%1,%2,%3};"
        : "+f"(c[0]), "+f"(c[1]), "+f"(c[2]), "+f"(c[3])
        : "r"(a[0]), "r"(a[1]), "r"(a[2]), "r"(a[3]), "r"(b[0]), "r"(b[1]));
}
__device__ __forceinline__ unsigned smem_u32(const void* p) {
    unsigned a;
    asm("{ .reg .u64 t; cvta.to.shared.u64 t, %1; cvt.u32.u64 %0, t; }" : "=r"(a) : "l"(p));
    return a;
}
__device__ __forceinline__ void ldsm4(unsigned& r0, unsigned& r1, unsigned& r2, unsigned& r3,
                                      unsigned addr) {
    asm volatile("ldmatrix.sync.aligned.m8n8.x4.shared.b16 {%0,%1,%2,%3}, [%4];"
                 : "=r"(r0), "=r"(r1), "=r"(r2), "=r"(r3) : "r"(addr));
}
__device__ __forceinline__ void cpa16(unsigned saddr, const void* g) {
    asm volatile("cp.async.cg.shared.global [%0], [%1], 16;" :: "r"(saddr), "l"(g));
}

// ===================================================================
// Conversion kernels
// ===================================================================
// fp32 -> fp16 elementwise (x for QKV gemm)
__global__ __launch_bounds__(256)
void conv_x(const float4* __restrict__ src, uint2* __restrict__ dst)
{
    size_t i = (size_t)(blockIdx.x * 256 + threadIdx.x);
    float4 v = src[i];
    dst[i] = make_uint2(h2u(v.x, v.y), h2u(v.z, v.w));
}

// weight transpose: src [K][N] fp32 -> dst [row_off + n][k] fp16
__global__ __launch_bounds__(256)
void tconv(const float* __restrict__ src, __half* __restrict__ dst,
           int K, int N, int row_off)
{
    __shared__ float t[32][33];
    int n0 = blockIdx.x * 32, k0 = blockIdx.y * 32;
    int tx = threadIdx.x & 31, ty = threadIdx.x >> 5;
#pragma unroll
    for (int i = 0; i < 4; i++)
        t[ty + i * 8][tx] = src[(size_t)(k0 + ty + i * 8) * N + n0 + tx];
    __syncthreads();
#pragma unroll
    for (int i = 0; i < 4; i++) {
        int n = ty + i * 8;
        dst[(size_t)(row_off + n0 + n) * K + k0 + tx] = __float2half_rn(t[tx][n]);
    }
}

// Q region of QKV -> fp16 with qscale folded
__global__ __launch_bounds__(256)
void conv_q(const float* __restrict__ QKV, uint2* __restrict__ dst)
{
    const float qscale = 0.125f * 1.44269504f;
    size_t i = (size_t)(blockIdx.x * 256 + threadIdx.x);   // float4 index within Q rows
    size_t row = i >> 9;               // 512 float4 per 2048-col row
    size_t c4  = i & 511;
    float4 v = *(const float4*)(QKV + row * QKVW + c4 * 4);
    dst[i] = make_uint2(h2u(v.x * qscale, v.y * qscale), h2u(v.z * qscale, v.w * qscale));
}

// K region of QKV -> fp16 [m][512]
__global__ __launch_bounds__(256)
void conv_k(const float* __restrict__ QKV, uint2* __restrict__ dst)
{
    size_t i = (size_t)(blockIdx.x * 256 + threadIdx.x);   // float4 index within K rows
    size_t row = i >> 7;               // 128 float4 per 512-col row
    size_t c4  = i & 127;
    float4 v = *(const float4*)(QKV + row * QKVW + 2048 + c4 * 4);
    dst[i] = make_uint2(h2u(v.x, v.y), h2u(v.z, v.w));
}

// V region -> transposed packed fp16: g_Vt[(b*KV+kv)*64 + d][n]  (pairs along n)
__global__ __launch_bounds__(256)
void conv_vt(const float* __restrict__ QKV, unsigned* __restrict__ dst)
{
    __shared__ float t[32][65];
    int n0  = blockIdx.x * 32;
    int bkv = blockIdx.y;               // 0..15
    int b   = bkv >> 3;
    int kv  = bkv & 7;
    int tid = threadIdx.x;
#pragma unroll
    for (int p = 0; p < 2; p++) {
        int id = tid + p * 256;
        int r  = id >> 4;               // 0..31 (n)
        int c4 = (id & 15) * 4;         // 0..60 (d)
        float4 v = *(const float4*)(QKV + (size_t)(b * N_ + n0 + r) * QKVW + 2560 + kv * 64 + c4);
        t[r][c4]     = v.x;
        t[r][c4 + 1] = v.y;
        t[r][c4 + 2] = v.z;
        t[r][c4 + 3] = v.w;
    }
    __syncthreads();
    int d  = tid >> 2;                  // 0..63
    int j4 = (tid & 3) * 4;             // word group
    unsigned w[4];
#pragma unroll
    for (int j = 0; j < 4; j++)
        w[j] = h2u(t[2 * (j4 + j)][d], t[2 * (j4 + j) + 1][d]);
    size_t off = (size_t)(bkv * 64 + d) * (N_ / 2) + n0 / 2 + j4;
    *(uint4*)(dst + off) = make_uint4(w[0], w[1], w[2], w[3]);
}

// ===================================================================
// fp16 GEMM: C[M,Nc] = A[M,K] @ B^T (B stored [Nc][K]).
// block 128x128, KT=64, 8 warps (2x4), warp tile 64x32,
// cp.async 2-stage + ldmatrix. 1 mma16 per (mt,nt,k16).
// ===================================================================
#define GST 36                        // words per row (32 data + 4 pad)
#define BUFW (128 * GST)
#define BUFB (BUFW * 4)               // 18432 B
#define STAGEB (2 * BUFB)             // 36864 B
#define GEMM_SMEMB (2 * STAGEB)       // 73728 B

__global__ __launch_bounds__(256)
void gemm_f16(const __half* __restrict__ Ag, const __half* __restrict__ Bg,
              float* __restrict__ C, const float* __restrict__ bias,
              int Nc, int K)
{
    extern __shared__ unsigned smw[];
    const unsigned sb = smem_u32(smw);

    const int tid  = threadIdx.x;
    const int lane = tid & 31;
    const int wid  = tid >> 5;
    const int wr   = (wid >> 2) * 64;
    const int wc   = (wid & 3) * 32;
    const int brow = blockIdx.y * 128;
    const int bcol = blockIdx.x * 128;
    const int q    = lane & 3;
    const int l4   = lane >> 2;
    const int Kw   = K >> 1;
    const int sub  = lane >> 3;
    const int r8   = lane & 7;

    const unsigned* Aw = (const unsigned*)Ag;
    const unsigned* Bw = (const unsigned*)Bg;

    float acc[4][4][4];
#pragma unroll
    for (int i = 0; i < 4; i++)
#pragma unroll
        for (int j = 0; j < 4; j++)
#pragma unroll
            for (int e = 0; e < 4; e++) acc[i][j][e] = 0.0f;

    const int nst = K / 64;

    auto issue = [&](int stage, int kw0) {
        unsigned sd = sb + stage * STAGEB;
#pragma unroll
        for (int p = 0; p < 4; p++) {
            int id = tid + p * 256;
            int r  = id >> 3;               // 0..127
            int c4 = (id & 7) * 4;          // word col
            unsigned o = (unsigned)(r * GST + c4) * 4;
            cpa16(sd + o,        Aw + (size_t)(brow + r) * Kw + kw0 + c4);
            cpa16(sd + BUFB + o, Bw + (size_t)(bcol + r) * Kw + kw0 + c4);
        }
        asm volatile("cp.async.commit_group;");
    };

    issue(0, 0);

    for (int i = 0; i < nst; i++) {
        if (i + 1 < nst) {
            issue((i + 1) & 1, (i + 1) * 32);
            asm volatile("cp.async.wait_group 1;");
        } else {
            asm volatile("cp.async.wait_group 0;");
        }
        __syncthreads();

        const unsigned sd = sb + (i & 1) * STAGEB;
        const unsigned sA = sd, sB = sd + BUFB;

#pragma unroll
        for (int ks2 = 0; ks2 < 32; ks2 += 8) {      // 4 k16 steps
            unsigned bh[4][2];
#pragma unroll
            for (int pr = 0; pr < 4; pr += 2) {
                int nrow = wc + (pr + (sub >> 1)) * 8 + r8;
                int colw = ks2 + (sub & 1) * 4;
                unsigned off = (unsigned)(nrow * GST + colw) * 4;
                ldsm4(bh[pr][0], bh[pr][1], bh[pr + 1][0], bh[pr + 1][1], sB + off);
            }
#pragma unroll
            for (int mt = 0; mt < 4; mt++) {
                int arow = wr + mt * 16 + (sub & 1) * 8 + r8;
                int colw = ks2 + (sub >> 1) * 4;
                unsigned off = (unsigned)(arow * GST + colw) * 4;
                unsigned ah[4];
                ldsm4(ah[0], ah[1], ah[2], ah[3], sA + off);
#pragma unroll
                for (int nt = 0; nt < 4; nt++)
                    mma16f(acc[mt][nt], ah, bh[nt]);
            }
        }
        __syncthreads();
    }

    // epilogue
#pragma unroll
    for (int mt = 0; mt < 4; mt++) {
#pragma unroll
        for (int nt = 0; nt < 4; nt++) {
            int row = brow + wr + mt * 16 + l4;
            int col = bcol + wc + nt * 8 + 2 * q;
            float b0 = 0.f, b1 = 0.f;
            if (bias) { b0 = bias[col]; b1 = bias[col + 1]; }
            float2 v0 = make_float2(acc[mt][nt][0] + b0, acc[mt][nt][1] + b1);
            float2 v1 = make_float2(acc[mt][nt][2] + b0, acc[mt][nt][3] + b1);
            *(float2*)(C + (size_t)row * Nc + col)       = v0;
            *(float2*)(C + (size_t)(row + 8) * Nc + col) = v1;
        }
    }
}

// ===================================================================
// Flash attention, all-fp16 MMAs. Block = 64 q rows of one (b,h).
// QK^T: 1xfp16 k16 (4 steps over DH=64). PV: 1xfp16 k16 (2 steps over 32 keys).
// Base-2 softmax. Writes ctx as fp16 for the out-projection.
// ===================================================================
#define FBM 64
#define FBN 32
#define KSW 36   // Ks stride in words
#define VTW 20   // VsT stride in words
#define PSW 20   // Ps stride in words

__global__ __launch_bounds__(128)
void flash16(const __half* __restrict__ Q16, const __half* __restrict__ K16,
             const __half* __restrict__ Vt, __half* __restrict__ c16)
{
    __shared__ unsigned Ks[FBN][KSW];       // [key][dh pairs]
    __shared__ unsigned VsT[DH_][VTW];      // [d][key pairs]
    __shared__ unsigned Ps[FBM][PSW];       // [q][key pairs]

    const int tid  = threadIdx.x;
    const int lane = tid & 31;
    const int wid  = tid >> 5;
    const int q    = lane & 3;
    const int l4   = lane >> 2;
    const int m0   = blockIdx.x * FBM;
    const int h    = blockIdx.y;
    const int b    = blockIdx.z;
    const int kv   = h >> 2;

    const int r0 = m0 + wid * 16 + l4;

    // Q fragments (fp16, qscale pre-folded): 4 k16 steps over DH=64
    const unsigned* Qw = (const unsigned*)Q16;
    unsigned qh[4][4];
    {
        size_t q0 = (size_t)(b * N_ + r0) * 1024 + h * 32;       // word base row r0
        size_t q1 = q0 + (size_t)8 * 1024;                       // row r0+8
#pragma unroll
        for (int ks = 0; ks < 4; ks++) {
            qh[ks][0] = Qw[q0 + ks * 8 + q];
            qh[ks][1] = Qw[q1 + ks * 8 + q];
            qh[ks][2] = Qw[q0 + ks * 8 + q + 4];
            qh[ks][3] = Qw[q1 + ks * 8 + q + 4];
        }
    }

    float oacc[8][4];
#pragma unroll
    for (int d = 0; d < 8; d++)
#pragma unroll
        for (int e = 0; e < 4; e++) oacc[d][e] = 0.0f;
    float mcur0 = -1e30f, mcur1 = -1e30f, l0 = 0.0f, l1 = 0.0f;

    const int rowmax = m0 + wid * 16 + 15;
    const int nend = m0 + FBM;

    const unsigned* Kw = (const unsigned*)K16;   // row stride 256 words
    const unsigned* Vw = (const unsigned*)Vt;    // row stride 1024 words
    const size_t kbase = (size_t)(b * N_) * 256 + kv * 32;
    const size_t vbase = (size_t)((b * KV_ + kv) * 64) * 1024;

    for (int n0 = 0; n0 < nend; n0 += FBN) {
        // K tile: 32 rows x 32 words
#pragma unroll
        for (int p = 0; p < 2; p++) {
            int id = tid + p * 128;
            int r  = id >> 3;
            int w4 = (id & 7) * 4;
            *(uint4*)&Ks[r][w4] = *(const uint4*)(Kw + kbase + (size_t)(n0 + r) * 256 + w4);
        }
        // V^T tile: 64 rows x 16 words
#pragma unroll
        for (int p = 0; p < 2; p++) {
            int id = tid + p * 128;
            int r  = id >> 2;
            int w4 = (id & 3) * 4;
            *(uint4*)&VsT[r][w4] = *(const uint4*)(Vw + vbase + (size_t)r * 1024 + n0 / 2 + w4);
        }
        __syncthreads();

        if (n0 <= rowmax) {
            // ---- S = Q K^T : 1xfp16, 4 k16 steps ----
            float s[4][4];
#pragma unroll
            for (int nt = 0; nt < 4; nt++)
#pragma unroll
                for (int e = 0; e < 4; e++) s[nt][e] = 0.0f;

#pragma unroll
            for (int ks = 0; ks < 4; ks++) {
                unsigned bh[4][2];
#pragma unroll
                for (int nt = 0; nt < 4; nt++) {
                    int n = nt * 8 + l4;
                    bh[nt][0] = Ks[n][ks * 8 + q];
                    bh[nt][1] = Ks[n][ks * 8 + q + 4];
                }
#pragma unroll
                for (int nt = 0; nt < 4; nt++)
                    mma16f(s[nt], qh[ks], bh[nt]);
            }

            // ---- causal mask + row max ----
            float mt0 = -1e30f, mt1 = -1e30f;
#pragma unroll
            for (int nt = 0; nt < 4; nt++) {
#pragma unroll
                for (int e = 0; e < 2; e++) {
                    int col = n0 + nt * 8 + 2 * q + e;
                    if (col > r0)     s[nt][e]     = -1e30f;
                    if (col > r0 + 8) s[nt][2 + e] = -1e30f;
                    mt0 = fmaxf(mt0, s[nt][e]);
                    mt1 = fmaxf(mt1, s[nt][2 + e]);
                }
            }
            mt0 = fmaxf(mt0, __shfl_xor_sync(0xffffffff, mt0, 1));
            mt0 = fmaxf(mt0, __shfl_xor_sync(0xffffffff, mt0, 2));
            mt1 = fmaxf(mt1, __shfl_xor_sync(0xffffffff, mt1, 1));
            mt1 = fmaxf(mt1, __shfl_xor_sync(0xffffffff, mt1, 2));

            float mn0 = fmaxf(mcur0, mt0);
            float mn1 = fmaxf(mcur1, mt1);
            float cr0 = exp2f(mcur0 - mn0);
            float cr1 = exp2f(mcur1 - mn1);
            l0 *= cr0; l1 *= cr1;
#pragma unroll
            for (int d = 0; d < 8; d++) {
                oacc[d][0] *= cr0; oacc[d][1] *= cr0;
                oacc[d][2] *= cr1; oacc[d][3] *= cr1;
            }

            int prow = wid * 16 + l4;
#pragma unroll
            for (int nt = 0; nt < 4; nt++) {
                float p00 = exp2f(s[nt][0] - mn0);
                float p01 = exp2f(s[nt][1] - mn0);
                float p10 = exp2f(s[nt][2] - mn1);
                float p11 = exp2f(s[nt][3] - mn1);
                l0 += p00 + p01;
                l1 += p10 + p11;
                Ps[prow][nt * 4 + q]     = h2u(p00, p01);
                Ps[prow + 8][nt * 4 + q] = h2u(p10, p11);
            }
            mcur0 = mn0; mcur1 = mn1;
            __syncwarp();

            // ---- O += P V : 1xfp16, 2 k16 steps over 32 keys ----
#pragma unroll
            for (int ks = 0; ks < 2; ks++) {
                unsigned a[4];
                a[0] = Ps[prow][ks * 8 + q];
                a[1] = Ps[prow + 8][ks * 8 + q];
                a[2] = Ps[prow][ks * 8 + q + 4];
                a[3] = Ps[prow + 8][ks * 8 + q + 4];
#pragma unroll
                for (int dt = 0; dt < 8; dt++) {
                    int nn = dt * 8 + l4;
                    unsigned bb[2];
                    bb[0] = VsT[nn][ks * 8 + q];
                    bb[1] = VsT[nn][ks * 8 + q + 4];
                    mma16f(oacc[dt], a, bb);
                }
            }
        }
        __syncthreads();
    }

    l0 += __shfl_xor_sync(0xffffffff, l0, 1);
    l0 += __shfl_xor_sync(0xffffffff, l0, 2);
    l1 += __shfl_xor_sync(0xffffffff, l1, 1);
    l1 += __shfl_xor_sync(0xffffffff, l1, 2);
    float inv0 = 1.0f / l0;
    float inv1 = 1.0f / l1;

    // write ctx as fp16 (A operand of out-projection)
    unsigned* cw = (unsigned*)c16;
    size_t c0 = (size_t)(b * N_ + r0) * 1024 + h * 32;
    size_t c1 = c0 + (size_t)8 * 1024;
#pragma unroll
    for (int dt = 0; dt < 8; dt++) {
        cw[c0 + dt * 4 + q] = h2u(oacc[dt][0] * inv0, oacc[dt][1] * inv0);
        cw[c1 + dt * 4 + q] = h2u(oacc[dt][2] * inv1, oacc[dt][3] * inv1);
    }
}

// ===================================================================
// Launch
// ===================================================================
extern "C" void kernel_launch(void* const* d_in, const int* in_sizes, int n_in,
                              void* d_out, int out_size)
{
    const float* x  = (const float*)d_in[0];
    const float* Wq = (const float*)d_in[1];
    const float* Wk = (const float*)d_in[2];
    const float* Wv = (const float*)d_in[3];
    const float* Wo = (const float*)d_in[4];
    const float* bo = (const float*)d_in[5];
    float* out = (float*)d_out;

    float *QKV;
    __half *x16, *Wqkv16, *Wo16, *Q16, *K16, *Vt, *c16;
    cudaGetSymbolAddress((void**)&QKV,    g_QKV);
    cudaGetSymbolAddress((void**)&x16,    g_x16);
    cudaGetSymbolAddress((void**)&Wqkv16, g_Wqkv16);
    cudaGetSymbolAddress((void**)&Wo16,   g_Wo16);
    cudaGetSymbolAddress((void**)&Q16,    g_Q16);
    cudaGetSymbolAddress((void**)&K16,    g_K16);
    cudaGetSymbolAddress((void**)&Vt,     g_Vt);
    cudaGetSymbolAddress((void**)&c16,    g_c16);

    cudaFuncSetAttribute(gemm_f16, cudaFuncAttributeMaxDynamicSharedMemorySize,
                         GEMM_SMEMB);

    // input conversions
    conv_x<<<(int)((size_t)M_ * DIN / 4 / 256), 256>>>((const float4*)x, (uint2*)x16);
    tconv<<<dim3(2048 / 32, DIN / 32), 256>>>(Wq, Wqkv16, DIN, 2048, 0);
    tconv<<<dim3(512 / 32,  DIN / 32), 256>>>(Wk, Wqkv16, DIN, 512, 2048);
    tconv<<<dim3(512 / 32,  DIN / 32), 256>>>(Wv, Wqkv16, DIN, 512, 2560);
    tconv<<<dim3(DIN / 32,  DOUT / 32), 256>>>(Wo, Wo16, DOUT, DIN, 0);

    // fused QKV projection
    gemm_f16<<<dim3(QKVW / 128, M_ / 128), 256, GEMM_SMEMB>>>(
        x16, Wqkv16, QKV, nullptr, QKVW, DIN);

    // Q/K/V conversions for flash
    conv_q<<<(int)((size_t)M_ * 2048 / 4 / 256), 256>>>(QKV, (uint2*)Q16);
    conv_k<<<(int)((size_t)M_ * 512 / 4 / 256), 256>>>(QKV, (uint2*)K16);
    conv_vt<<<dim3(N_ / 32, B_ * KV_), 256>>>(QKV, (unsigned*)Vt);

    // attention
    flash16<<<dim3(N_ / FBM, H_, B_), 128>>>(Q16, K16, Vt, c16);

    // output projection + bias
    gemm_f16<<<dim3(DIN / 128, M_ / 128), 256, GEMM_SMEMB>>>(
        c16, Wo16, out, bo, DIN, DOUT);
}

// round 9
// speedup vs baseline: 9.2654x; 1.0549x over previous
#include <cuda_runtime.h>
#include <cuda_bf16.h>
#include <cuda_fp16.h>
#include <cstdint>
#include <math.h>

// Problem constants
#define B_   2
#define N_   2048
#define DIN  2048
#define DOUT 2048
#define H_   32
#define KV_  8
#define DH_  64
#define M_   (B_ * N_)          // 4096
#define QKVW 3072               // fused Q|K|V output width

// -------- scratch (allocation-free rule: __device__ globals) --------
__device__ __align__(16) __half g_x16[(size_t)M_ * DIN];          // A for QKV gemm
__device__ __align__(16) __half g_Wqkv16[(size_t)QKVW * DIN];     // [n][k]
__device__ __align__(16) __half g_Wo16[(size_t)DIN * DOUT];       // [n][k]
__device__ __align__(16) __half g_QKV16[(size_t)M_ * QKVW];       // fused fp16 proj out
__device__ __align__(16) __half g_c16[(size_t)M_ * DOUT];         // ctx fp16

// ---------------- helpers ----------------
__device__ __forceinline__ unsigned h2u(float a, float b) {
    __half2 h = __floats2half2_rn(a, b);
    return *reinterpret_cast<unsigned*>(&h);
}
__device__ __forceinline__ void mma16f(float c[4], const unsigned a[4], const unsigned b[2]) {
    asm volatile(
        "mma.sync.aligned.m16n8k16.row.col.f32.f16.f16.f32 "
        "{%0,%1,%2,%3}, {%4,%5,%6,%7}, {%8,%9}, {%0,%1,%2,%3};"
        : "+f"(c[0]), "+f"(c[1]), "+f"(c[2]), "+f"(c[3])
        : "r"(a[0]), "r"(a[1]), "r"(a[2]), "r"(a[3]), "r"(b[0]), "r"(b[1]));
}
__device__ __forceinline__ unsigned smem_u32(const void* p) {
    unsigned a;
    asm("{ .reg .u64 t; cvta.to.shared.u64 t, %1; cvt.u32.u64 %0, t; }" : "=r"(a) : "l"(p));
    return a;
}
__device__ __forceinline__ void ldsm4(unsigned& r0, unsigned& r1, unsigned& r2, unsigned& r3,
                                      unsigned addr) {
    asm volatile("ldmatrix.sync.aligned.m8n8.x4.shared.b16 {%0,%1,%2,%3}, [%4];"
                 : "=r"(r0), "=r"(r1), "=r"(r2), "=r"(r3) : "r"(addr));
}
__device__ __forceinline__ void ldsm4t(unsigned& r0, unsigned& r1, unsigned& r2, unsigned& r3,
                                       unsigned addr) {
    asm volatile("ldmatrix.sync.aligned.m8n8.x4.trans.shared.b16 {%0,%1,%2,%3}, [%4];"
                 : "=r"(r0), "=r"(r1), "=r"(r2), "=r"(r3) : "r"(addr));
}
__device__ __forceinline__ void cpa16(unsigned saddr, const void* g) {
    asm volatile("cp.async.cg.shared.global [%0], [%1], 16;" :: "r"(saddr), "l"(g));
}

// ===================================================================
// Conversion kernels (inputs only)
// ===================================================================
__global__ __launch_bounds__(256)
void conv_x(const float4* __restrict__ src, uint2* __restrict__ dst)
{
    size_t i = (size_t)(blockIdx.x * 256 + threadIdx.x);
    float4 v = src[i];
    dst[i] = make_uint2(h2u(v.x, v.y), h2u(v.z, v.w));
}

__global__ __launch_bounds__(256)
void tconv(const float* __restrict__ src, __half* __restrict__ dst,
           int K, int N, int row_off)
{
    __shared__ float t[32][33];
    int n0 = blockIdx.x * 32, k0 = blockIdx.y * 32;
    int tx = threadIdx.x & 31, ty = threadIdx.x >> 5;
#pragma unroll
    for (int i = 0; i < 4; i++)
        t[ty + i * 8][tx] = src[(size_t)(k0 + ty + i * 8) * N + n0 + tx];
    __syncthreads();
#pragma unroll
    for (int i = 0; i < 4; i++) {
        int n = ty + i * 8;
        dst[(size_t)(row_off + n0 + n) * K + k0 + tx] = __float2half_rn(t[tx][n]);
    }
}

// ===================================================================
// fp16 GEMM: C[M,Nc] = A[M,K] @ B^T (B stored [Nc][K]).
// block 128x128, KT=64, 8 warps (2x4), warp tile 64x32,
// cp.async 2-stage + ldmatrix.
// Output: either fp32 C (+bias) or fp16 Ch (cols < scaleCols scaled).
// ===================================================================
#define GST 36                        // words per row (32 data + 4 pad)
#define BUFW (128 * GST)
#define BUFB (BUFW * 4)
#define STAGEB (2 * BUFB)
#define GEMM_SMEMB (2 * STAGEB)       // 73728 B

__global__ __launch_bounds__(256)
void gemm_f16(const __half* __restrict__ Ag, const __half* __restrict__ Bg,
              float* __restrict__ Cf, __half* __restrict__ Ch,
              const float* __restrict__ bias,
              int Nc, int K, int scaleCols, float scaleVal)
{
    extern __shared__ unsigned smw[];
    const unsigned sb = smem_u32(smw);

    const int tid  = threadIdx.x;
    const int lane = tid & 31;
    const int wid  = tid >> 5;
    const int wr   = (wid >> 2) * 64;
    const int wc   = (wid & 3) * 32;
    const int brow = blockIdx.y * 128;
    const int bcol = blockIdx.x * 128;
    const int q    = lane & 3;
    const int l4   = lane >> 2;
    const int Kw   = K >> 1;
    const int sub  = lane >> 3;
    const int r8   = lane & 7;

    const unsigned* Aw = (const unsigned*)Ag;
    const unsigned* Bw = (const unsigned*)Bg;

    float acc[4][4][4];
#pragma unroll
    for (int i = 0; i < 4; i++)
#pragma unroll
        for (int j = 0; j < 4; j++)
#pragma unroll
            for (int e = 0; e < 4; e++) acc[i][j][e] = 0.0f;

    const int nst = K / 64;

    auto issue = [&](int stage, int kw0) {
        unsigned sd = sb + stage * STAGEB;
#pragma unroll
        for (int p = 0; p < 4; p++) {
            int id = tid + p * 256;
            int r  = id >> 3;
            int c4 = (id & 7) * 4;
            unsigned o = (unsigned)(r * GST + c4) * 4;
            cpa16(sd + o,        Aw + (size_t)(brow + r) * Kw + kw0 + c4);
            cpa16(sd + BUFB + o, Bw + (size_t)(bcol + r) * Kw + kw0 + c4);
        }
        asm volatile("cp.async.commit_group;");
    };

    issue(0, 0);

    for (int i = 0; i < nst; i++) {
        if (i + 1 < nst) {
            issue((i + 1) & 1, (i + 1) * 32);
            asm volatile("cp.async.wait_group 1;");
        } else {
            asm volatile("cp.async.wait_group 0;");
        }
        __syncthreads();

        const unsigned sd = sb + (i & 1) * STAGEB;
        const unsigned sA = sd, sB = sd + BUFB;

#pragma unroll
        for (int ks2 = 0; ks2 < 32; ks2 += 8) {
            unsigned bh[4][2];
#pragma unroll
            for (int pr = 0; pr < 4; pr += 2) {
                int nrow = wc + (pr + (sub >> 1)) * 8 + r8;
                int colw = ks2 + (sub & 1) * 4;
                unsigned off = (unsigned)(nrow * GST + colw) * 4;
                ldsm4(bh[pr][0], bh[pr][1], bh[pr + 1][0], bh[pr + 1][1], sB + off);
            }
#pragma unroll
            for (int mt = 0; mt < 4; mt++) {
                int arow = wr + mt * 16 + (sub & 1) * 8 + r8;
                int colw = ks2 + (sub >> 1) * 4;
                unsigned off = (unsigned)(arow * GST + colw) * 4;
                unsigned ah[4];
                ldsm4(ah[0], ah[1], ah[2], ah[3], sA + off);
#pragma unroll
                for (int nt = 0; nt < 4; nt++)
                    mma16f(acc[mt][nt], ah, bh[nt]);
            }
        }
        __syncthreads();
    }

    // epilogue
    if (Ch) {
        unsigned* Chw = (unsigned*)Ch;
        const int Ncw = Nc >> 1;
#pragma unroll
        for (int mt = 0; mt < 4; mt++) {
#pragma unroll
            for (int nt = 0; nt < 4; nt++) {
                int row = brow + wr + mt * 16 + l4;
                int col = bcol + wc + nt * 8 + 2 * q;
                float sc = (col < scaleCols) ? scaleVal : 1.0f;
                Chw[(size_t)row * Ncw + (col >> 1)] =
                    h2u(acc[mt][nt][0] * sc, acc[mt][nt][1] * sc);
                Chw[(size_t)(row + 8) * Ncw + (col >> 1)] =
                    h2u(acc[mt][nt][2] * sc, acc[mt][nt][3] * sc);
            }
        }
    } else {
#pragma unroll
        for (int mt = 0; mt < 4; mt++) {
#pragma unroll
            for (int nt = 0; nt < 4; nt++) {
                int row = brow + wr + mt * 16 + l4;
                int col = bcol + wc + nt * 8 + 2 * q;
                float b0 = 0.f, b1 = 0.f;
                if (bias) { b0 = bias[col]; b1 = bias[col + 1]; }
                *(float2*)(Cf + (size_t)row * Nc + col) =
                    make_float2(acc[mt][nt][0] + b0, acc[mt][nt][1] + b1);
                *(float2*)(Cf + (size_t)(row + 8) * Nc + col) =
                    make_float2(acc[mt][nt][2] + b0, acc[mt][nt][3] + b1);
            }
        }
    }
}

// ===================================================================
// Flash attention, all-fp16 MMAs, reading the fused fp16 QKV buffer.
// Block = 128 q rows of one (b,h), 8 warps x 16 rows. Key tiles of 32.
// V row-major tile + ldmatrix.trans for PV b-frags.
// ===================================================================
#define FBM 128
#define FBN 32
#define KSW 36   // Ks row stride (words)
#define VSW 36   // Vs row stride (words); bytes = 144
#define PSW 20   // Ps row stride (words)

__global__ __launch_bounds__(256)
void flash16(const __half* __restrict__ QKV16, __half* __restrict__ c16)
{
    __shared__ unsigned Ks[FBN][KSW];       // [key][dh pairs]
    __shared__ unsigned Vs[FBN][VSW];       // [key][dh pairs] (row-major)
    __shared__ unsigned Ps[FBM][PSW];       // [q][key pairs]

    const int tid  = threadIdx.x;
    const int lane = tid & 31;
    const int wid  = tid >> 5;              // 0..7
    const int q    = lane & 3;
    const int l4   = lane >> 2;
    const int sub  = lane >> 3;
    const int r8   = lane & 7;
    const int m0   = blockIdx.x * FBM;
    const int h    = blockIdx.y;
    const int b    = blockIdx.z;
    const int kv   = h >> 2;

    const int r0 = m0 + wid * 16 + l4;
    const unsigned* W = (const unsigned*)QKV16;   // word ptr, row stride 1536
    const unsigned sbV = smem_u32(Vs);

    // Q fragments (qscale pre-folded in gemm epilogue)
    unsigned qh[4][4];
    {
        size_t q0 = (size_t)(b * N_ + r0) * 1536 + h * 32;
        size_t q1 = q0 + (size_t)8 * 1536;
#pragma unroll
        for (int ks = 0; ks < 4; ks++) {
            qh[ks][0] = W[q0 + ks * 8 + q];
            qh[ks][1] = W[q1 + ks * 8 + q];
            qh[ks][2] = W[q0 + ks * 8 + q + 4];
            qh[ks][3] = W[q1 + ks * 8 + q + 4];
        }
    }

    float oacc[8][4];
#pragma unroll
    for (int d = 0; d < 8; d++)
#pragma unroll
        for (int e = 0; e < 4; e++) oacc[d][e] = 0.0f;
    float mcur0 = -1e30f, mcur1 = -1e30f, l0 = 0.0f, l1 = 0.0f;

    const int rowmax = m0 + wid * 16 + 15;
    const int nend = m0 + FBM;
    const int prow = wid * 16 + l4;

    for (int n0 = 0; n0 < nend; n0 += FBN) {
        // K/V tiles: 32 rows x 8 uint4 each; 256 threads -> one uint4 per tile
        {
            int r  = tid >> 3;
            int w4 = (tid & 7) * 4;
            size_t rowbase = (size_t)(b * N_ + n0 + r) * 1536 + kv * 32;
            *(uint4*)&Ks[r][w4] = *(const uint4*)(W + rowbase + 1024 + w4);
            *(uint4*)&Vs[r][w4] = *(const uint4*)(W + rowbase + 1280 + w4);
        }
        __syncthreads();

        if (n0 <= rowmax) {
            // ---- S = Q K^T : 4 k16 steps ----
            float s[4][4];
#pragma unroll
            for (int nt = 0; nt < 4; nt++)
#pragma unroll
                for (int e = 0; e < 4; e++) s[nt][e] = 0.0f;

#pragma unroll
            for (int ks = 0; ks < 4; ks++) {
                unsigned bh[4][2];
#pragma unroll
                for (int nt = 0; nt < 4; nt++) {
                    int n = nt * 8 + l4;
                    bh[nt][0] = Ks[n][ks * 8 + q];
                    bh[nt][1] = Ks[n][ks * 8 + q + 4];
                }
#pragma unroll
                for (int nt = 0; nt < 4; nt++)
                    mma16f(s[nt], qh[ks], bh[nt]);
            }

            // ---- causal mask + row max ----
            float mt0 = -1e30f, mt1 = -1e30f;
#pragma unroll
            for (int nt = 0; nt < 4; nt++) {
#pragma unroll
                for (int e = 0; e < 2; e++) {
                    int col = n0 + nt * 8 + 2 * q + e;
                    if (col > r0)     s[nt][e]     = -1e30f;
                    if (col > r0 + 8) s[nt][2 + e] = -1e30f;
                    mt0 = fmaxf(mt0, s[nt][e]);
                    mt1 = fmaxf(mt1, s[nt][2 + e]);
                }
            }
            mt0 = fmaxf(mt0, __shfl_xor_sync(0xffffffff, mt0, 1));
            mt0 = fmaxf(mt0, __shfl_xor_sync(0xffffffff, mt0, 2));
            mt1 = fmaxf(mt1, __shfl_xor_sync(0xffffffff, mt1, 1));
            mt1 = fmaxf(mt1, __shfl_xor_sync(0xffffffff, mt1, 2));

            float mn0 = fmaxf(mcur0, mt0);
            float mn1 = fmaxf(mcur1, mt1);
            float cr0 = exp2f(mcur0 - mn0);
            float cr1 = exp2f(mcur1 - mn1);
            l0 *= cr0; l1 *= cr1;
#pragma unroll
            for (int d = 0; d < 8; d++) {
                oacc[d][0] *= cr0; oacc[d][1] *= cr0;
                oacc[d][2] *= cr1; oacc[d][3] *= cr1;
            }

#pragma unroll
            for (int nt = 0; nt < 4; nt++) {
                float p00 = exp2f(s[nt][0] - mn0);
                float p01 = exp2f(s[nt][1] - mn0);
                float p10 = exp2f(s[nt][2] - mn1);
                float p11 = exp2f(s[nt][3] - mn1);
                l0 += p00 + p01;
                l1 += p10 + p11;
                Ps[prow][nt * 4 + q]     = h2u(p00, p01);
                Ps[prow + 8][nt * 4 + q] = h2u(p10, p11);
            }
            mcur0 = mn0; mcur1 = mn1;
            __syncwarp();

            // ---- O += P V : 2 k16 steps, V b-frags via ldmatrix.trans ----
#pragma unroll
            for (int ks = 0; ks < 2; ks++) {
                unsigned a[4];
                a[0] = Ps[prow][ks * 8 + q];
                a[1] = Ps[prow + 8][ks * 8 + q];
                a[2] = Ps[prow][ks * 8 + q + 4];
                a[3] = Ps[prow + 8][ks * 8 + q + 4];
                int vrow = ks * 16 + (sub & 1) * 8 + r8;
#pragma unroll
                for (int dtp = 0; dtp < 4; dtp++) {
                    unsigned v0, v1, v2, v3;
                    unsigned addr = sbV + (unsigned)(vrow * (VSW * 4))
                                  + (unsigned)((dtp * 16 + (sub >> 1) * 8) * 2);
                    ldsm4t(v0, v1, v2, v3, addr);
                    unsigned b0[2] = {v0, v1};
                    unsigned b1[2] = {v2, v3};
                    mma16f(oacc[2 * dtp],     a, b0);
                    mma16f(oacc[2 * dtp + 1], a, b1);
                }
            }
        }
        __syncthreads();
    }

    l0 += __shfl_xor_sync(0xffffffff, l0, 1);
    l0 += __shfl_xor_sync(0xffffffff, l0, 2);
    l1 += __shfl_xor_sync(0xffffffff, l1, 1);
    l1 += __shfl_xor_sync(0xffffffff, l1, 2);
    float inv0 = 1.0f / l0;
    float inv1 = 1.0f / l1;

    unsigned* cw = (unsigned*)c16;
    size_t c0 = (size_t)(b * N_ + r0) * 1024 + h * 32;
    size_t c1 = c0 + (size_t)8 * 1024;
#pragma unroll
    for (int dt = 0; dt < 8; dt++) {
        cw[c0 + dt * 4 + q] = h2u(oacc[dt][0] * inv0, oacc[dt][1] * inv0);
        cw[c1 + dt * 4 + q] = h2u(oacc[dt][2] * inv1, oacc[dt][3] * inv1);
    }
}

// ===================================================================
// Launch
// ===================================================================
extern "C" void kernel_launch(void* const* d_in, const int* in_sizes, int n_in,
                              void* d_out, int out_size)
{
    const float* x  = (const float*)d_in[0];
    const float* Wq = (const float*)d_in[1];
    const float* Wk = (const float*)d_in[2];
    const float* Wv = (const float*)d_in[3];
    const float* Wo = (const float*)d_in[4];
    const float* bo = (const float*)d_in[5];
    float* out = (float*)d_out;

    __half *x16, *Wqkv16, *Wo16, *QKV16, *c16;
    cudaGetSymbolAddress((void**)&x16,    g_x16);
    cudaGetSymbolAddress((void**)&Wqkv16, g_Wqkv16);
    cudaGetSymbolAddress((void**)&Wo16,   g_Wo16);
    cudaGetSymbolAddress((void**)&QKV16,  g_QKV16);
    cudaGetSymbolAddress((void**)&c16,    g_c16);

    cudaFuncSetAttribute(gemm_f16, cudaFuncAttributeMaxDynamicSharedMemorySize,
                         GEMM_SMEMB);

    const float qscale = 0.125f * 1.44269504f;

    // input conversions
    conv_x<<<(int)((size_t)M_ * DIN / 4 / 256), 256>>>((const float4*)x, (uint2*)x16);
    tconv<<<dim3(2048 / 32, DIN / 32), 256>>>(Wq, Wqkv16, DIN, 2048, 0);
    tconv<<<dim3(512 / 32,  DIN / 32), 256>>>(Wk, Wqkv16, DIN, 512, 2048);
    tconv<<<dim3(512 / 32,  DIN / 32), 256>>>(Wv, Wqkv16, DIN, 512, 2560);
    tconv<<<dim3(DIN / 32,  DOUT / 32), 256>>>(Wo, Wo16, DOUT, DIN, 0);

    // fused QKV projection -> fp16 (Q columns pre-scaled by qscale)
    gemm_f16<<<dim3(QKVW / 128, M_ / 128), 256, GEMM_SMEMB>>>(
        x16, Wqkv16, nullptr, QKV16, nullptr, QKVW, DIN, 2048, qscale);

    // attention
    flash16<<<dim3(N_ / FBM, H_, B_), 256>>>(QKV16, c16);

    // output projection + bias -> fp32 out
    gemm_f16<<<dim3(DIN / 128, M_ / 128), 256, GEMM_SMEMB>>>(
        c16, Wo16, out, nullptr, bo, DIN, DOUT, 0, 1.0f);
}

// round 10
// speedup vs baseline: 9.8774x; 1.0660x over previous
#include <cuda_runtime.h>
#include <cuda_bf16.h>
#include <cuda_fp16.h>
#include <cstdint>
#include <math.h>

// Problem constants
#define B_   2
#define N_   2048
#define DIN  2048
#define DOUT 2048
#define H_   32
#define KV_  8
#define DH_  64
#define M_   (B_ * N_)          // 4096
#define QKVW 3072               // fused Q|K|V output width

// -------- scratch (allocation-free rule: __device__ globals) --------
__device__ __align__(16) __half g_x16[(size_t)M_ * DIN];          // A for QKV gemm
__device__ __align__(16) __half g_Wqkv16[(size_t)QKVW * DIN];     // [n][k]
__device__ __align__(16) __half g_Wo16[(size_t)DIN * DOUT];       // [n][k]
__device__ __align__(16) __half g_QKV16[(size_t)M_ * QKVW];       // fused fp16 proj out
__device__ __align__(16) __half g_c16[(size_t)M_ * DOUT];         // ctx fp16

// ---------------- helpers ----------------
__device__ __forceinline__ unsigned h2u(float a, float b) {
    __half2 h = __floats2half2_rn(a, b);
    return *reinterpret_cast<unsigned*>(&h);
}
__device__ __forceinline__ void mma16f(float c[4], const unsigned a[4], const unsigned b[2]) {
    asm volatile(
        "mma.sync.aligned.m16n8k16.row.col.f32.f16.f16.f32 "
        "{%0,%1,%2,%3}, {%4,%5,%6,%7}, {%8,%9}, {%0,%1,%2,%3};"
        : "+f"(c[0]), "+f"(c[1]), "+f"(c[2]), "+f"(c[3])
        : "r"(a[0]), "r"(a[1]), "r"(a[2]), "r"(a[3]), "r"(b[0]), "r"(b[1]));
}
__device__ __forceinline__ unsigned smem_u32(const void* p) {
    unsigned a;
    asm("{ .reg .u64 t; cvta.to.shared.u64 t, %1; cvt.u32.u64 %0, t; }" : "=r"(a) : "l"(p));
    return a;
}
__device__ __forceinline__ void ldsm4(unsigned& r0, unsigned& r1, unsigned& r2, unsigned& r3,
                                      unsigned addr) {
    asm volatile("ldmatrix.sync.aligned.m8n8.x4.shared.b16 {%0,%1,%2,%3}, [%4];"
                 : "=r"(r0), "=r"(r1), "=r"(r2), "=r"(r3) : "r"(addr));
}
__device__ __forceinline__ void ldsm4t(unsigned& r0, unsigned& r1, unsigned& r2, unsigned& r3,
                                       unsigned addr) {
    asm volatile("ldmatrix.sync.aligned.m8n8.x4.trans.shared.b16 {%0,%1,%2,%3}, [%4];"
                 : "=r"(r0), "=r"(r1), "=r"(r2), "=r"(r3) : "r"(addr));
}
__device__ __forceinline__ void cpa16(unsigned saddr, const void* g) {
    asm volatile("cp.async.cg.shared.global [%0], [%1], 16;" :: "r"(saddr), "l"(g));
}

// ===================================================================
// Conversion kernels (inputs only)
// ===================================================================
__global__ __launch_bounds__(256)
void conv_x(const float4* __restrict__ src, uint2* __restrict__ dst)
{
    size_t i = (size_t)(blockIdx.x * 256 + threadIdx.x);
    float4 v = src[i];
    dst[i] = make_uint2(h2u(v.x, v.y), h2u(v.z, v.w));
}

// all four weight transposes in one launch (linear region map)
__global__ __launch_bounds__(256)
void tconv_all(const float* __restrict__ Wq, const float* __restrict__ Wk,
               const float* __restrict__ Wv, const float* __restrict__ Wo,
               __half* __restrict__ Wqkv16, __half* __restrict__ Wo16)
{
    int bid = blockIdx.x;
    const float* src; __half* dst; int K, N, row_off;
    if (bid < 4096)      { src = Wq; dst = Wqkv16; K = DIN;  N = 2048; row_off = 0; }
    else if (bid < 5120) { src = Wk; dst = Wqkv16; K = DIN;  N = 512;  row_off = 2048; bid -= 4096; }
    else if (bid < 6144) { src = Wv; dst = Wqkv16; K = DIN;  N = 512;  row_off = 2560; bid -= 5120; }
    else                 { src = Wo; dst = Wo16;   K = DOUT; N = DIN;  row_off = 0;    bid -= 6144; }
    int ntn = N / 32;
    int n0 = (bid % ntn) * 32, k0 = (bid / ntn) * 32;

    __shared__ float t[32][33];
    int tx = threadIdx.x & 31, ty = threadIdx.x >> 5;
#pragma unroll
    for (int i = 0; i < 4; i++)
        t[ty + i * 8][tx] = src[(size_t)(k0 + ty + i * 8) * N + n0 + tx];
    __syncthreads();
#pragma unroll
    for (int i = 0; i < 4; i++) {
        int n = ty + i * 8;
        dst[(size_t)(row_off + n0 + n) * K + k0 + tx] = __float2half_rn(t[tx][n]);
    }
}

// ===================================================================
// fp16 GEMM: C[M,Nc] = A[M,K] @ B^T (B stored [Nc][K]).
// block 128x128, KT=64, 8 warps (2x4), warp tile 64x32,
// cp.async 2-stage + ldmatrix. (unchanged from R9)
// ===================================================================
#define GST 36
#define BUFW (128 * GST)
#define BUFB (BUFW * 4)
#define STAGEB (2 * BUFB)
#define GEMM_SMEMB (2 * STAGEB)       // 73728 B

__global__ __launch_bounds__(256)
void gemm_f16(const __half* __restrict__ Ag, const __half* __restrict__ Bg,
              float* __restrict__ Cf, __half* __restrict__ Ch,
              const float* __restrict__ bias,
              int Nc, int K, int scaleCols, float scaleVal)
{
    extern __shared__ unsigned smw[];
    const unsigned sb = smem_u32(smw);

    const int tid  = threadIdx.x;
    const int lane = tid & 31;
    const int wid  = tid >> 5;
    const int wr   = (wid >> 2) * 64;
    const int wc   = (wid & 3) * 32;
    const int brow = blockIdx.y * 128;
    const int bcol = blockIdx.x * 128;
    const int q    = lane & 3;
    const int l4   = lane >> 2;
    const int Kw   = K >> 1;
    const int sub  = lane >> 3;
    const int r8   = lane & 7;

    const unsigned* Aw = (const unsigned*)Ag;
    const unsigned* Bw = (const unsigned*)Bg;

    float acc[4][4][4];
#pragma unroll
    for (int i = 0; i < 4; i++)
#pragma unroll
        for (int j = 0; j < 4; j++)
#pragma unroll
            for (int e = 0; e < 4; e++) acc[i][j][e] = 0.0f;

    const int nst = K / 64;

    auto issue = [&](int stage, int kw0) {
        unsigned sd = sb + stage * STAGEB;
#pragma unroll
        for (int p = 0; p < 4; p++) {
            int id = tid + p * 256;
            int r  = id >> 3;
            int c4 = (id & 7) * 4;
            unsigned o = (unsigned)(r * GST + c4) * 4;
            cpa16(sd + o,        Aw + (size_t)(brow + r) * Kw + kw0 + c4);
            cpa16(sd + BUFB + o, Bw + (size_t)(bcol + r) * Kw + kw0 + c4);
        }
        asm volatile("cp.async.commit_group;");
    };

    issue(0, 0);

    for (int i = 0; i < nst; i++) {
        if (i + 1 < nst) {
            issue((i + 1) & 1, (i + 1) * 32);
            asm volatile("cp.async.wait_group 1;");
        } else {
            asm volatile("cp.async.wait_group 0;");
        }
        __syncthreads();

        const unsigned sd = sb + (i & 1) * STAGEB;
        const unsigned sA = sd, sB = sd + BUFB;

#pragma unroll
        for (int ks2 = 0; ks2 < 32; ks2 += 8) {
            unsigned bh[4][2];
#pragma unroll
            for (int pr = 0; pr < 4; pr += 2) {
                int nrow = wc + (pr + (sub >> 1)) * 8 + r8;
                int colw = ks2 + (sub & 1) * 4;
                unsigned off = (unsigned)(nrow * GST + colw) * 4;
                ldsm4(bh[pr][0], bh[pr][1], bh[pr + 1][0], bh[pr + 1][1], sB + off);
            }
#pragma unroll
            for (int mt = 0; mt < 4; mt++) {
                int arow = wr + mt * 16 + (sub & 1) * 8 + r8;
                int colw = ks2 + (sub >> 1) * 4;
                unsigned off = (unsigned)(arow * GST + colw) * 4;
                unsigned ah[4];
                ldsm4(ah[0], ah[1], ah[2], ah[3], sA + off);
#pragma unroll
                for (int nt = 0; nt < 4; nt++)
                    mma16f(acc[mt][nt], ah, bh[nt]);
            }
        }
        __syncthreads();
    }

    if (Ch) {
        unsigned* Chw = (unsigned*)Ch;
        const int Ncw = Nc >> 1;
#pragma unroll
        for (int mt = 0; mt < 4; mt++) {
#pragma unroll
            for (int nt = 0; nt < 4; nt++) {
                int row = brow + wr + mt * 16 + l4;
                int col = bcol + wc + nt * 8 + 2 * q;
                float sc = (col < scaleCols) ? scaleVal : 1.0f;
                Chw[(size_t)row * Ncw + (col >> 1)] =
                    h2u(acc[mt][nt][0] * sc, acc[mt][nt][1] * sc);
                Chw[(size_t)(row + 8) * Ncw + (col >> 1)] =
                    h2u(acc[mt][nt][2] * sc, acc[mt][nt][3] * sc);
            }
        }
    } else {
#pragma unroll
        for (int mt = 0; mt < 4; mt++) {
#pragma unroll
            for (int nt = 0; nt < 4; nt++) {
                int row = brow + wr + mt * 16 + l4;
                int col = bcol + wc + nt * 8 + 2 * q;
                float b0 = 0.f, b1 = 0.f;
                if (bias) { b0 = bias[col]; b1 = bias[col + 1]; }
                *(float2*)(Cf + (size_t)row * Nc + col) =
                    make_float2(acc[mt][nt][0] + b0, acc[mt][nt][1] + b1);
                *(float2*)(Cf + (size_t)(row + 8) * Nc + col) =
                    make_float2(acc[mt][nt][2] + b0, acc[mt][nt][3] + b1);
            }
        }
    }
}

// ===================================================================
// Flash attention: FBM=128 q rows, FBN=64 key tiles, 8 warps x 16 rows.
// cp.async double-buffered K/V tiles. All-fp16 MMAs.
// ===================================================================
#define FBM 128
#define FBN 64
#define KSW 36                        // K/V row stride (words)
#define PSW 36                        // Ps row stride (words)
#define KBUF (FBN * KSW * 4)          // 9216 B per K (or V) buffer
#define FSTAGE (2 * KBUF)             // 18432 B per stage (K+V)
#define PS_OFF (2 * FSTAGE)           // Ps after the two stages
#define FLASH_SMEMB (PS_OFF + FBM * PSW * 4)   // 36864 + 18432 = 55296 B

__global__ __launch_bounds__(256)
void flash16(const __half* __restrict__ QKV16, __half* __restrict__ c16)
{
    extern __shared__ char fsm[];
    const unsigned sbd = smem_u32(fsm);
    unsigned* Psp = (unsigned*)(fsm + PS_OFF);

    const int tid  = threadIdx.x;
    const int lane = tid & 31;
    const int wid  = tid >> 5;              // 0..7
    const int q    = lane & 3;
    const int l4   = lane >> 2;
    const int sub  = lane >> 3;
    const int r8   = lane & 7;
    const int m0   = blockIdx.x * FBM;
    const int h    = blockIdx.y;
    const int b    = blockIdx.z;
    const int kv   = h >> 2;

    const int r0 = m0 + wid * 16 + l4;
    const unsigned* W = (const unsigned*)QKV16;   // word ptr, row stride 1536

    // Q fragments (qscale pre-folded in gemm epilogue)
    unsigned qh[4][4];
    {
        size_t q0 = (size_t)(b * N_ + r0) * 1536 + h * 32;
        size_t q1 = q0 + (size_t)8 * 1536;
#pragma unroll
        for (int ks = 0; ks < 4; ks++) {
            qh[ks][0] = W[q0 + ks * 8 + q];
            qh[ks][1] = W[q1 + ks * 8 + q];
            qh[ks][2] = W[q0 + ks * 8 + q + 4];
            qh[ks][3] = W[q1 + ks * 8 + q + 4];
        }
    }

    float oacc[8][4];
#pragma unroll
    for (int d = 0; d < 8; d++)
#pragma unroll
        for (int e = 0; e < 4; e++) oacc[d][e] = 0.0f;
    float mcur0 = -1e30f, mcur1 = -1e30f, l0 = 0.0f, l1 = 0.0f;

    const int rowmax = m0 + wid * 16 + 15;
    const int ntiles = (m0 + FBM) / FBN;          // m0/64 + 2
    const int prow = wid * 16 + l4;

    // stage issue: K/V tile of 64 rows x 8 uint4 each; 2 per thread per tensor
    auto fissue = [&](int stage, int n0) {
        unsigned sd = sbd + stage * FSTAGE;
#pragma unroll
        for (int p = 0; p < 2; p++) {
            int id = tid + p * 256;
            int r  = id >> 3;
            int w4 = (id & 7) * 4;
            size_t rowbase = (size_t)(b * N_ + n0 + r) * 1536 + kv * 32;
            unsigned o = (unsigned)(r * KSW + w4) * 4;
            cpa16(sd + o,        W + rowbase + 1024 + w4);   // K
            cpa16(sd + KBUF + o, W + rowbase + 1280 + w4);   // V
        }
        asm volatile("cp.async.commit_group;");
    };

    fissue(0, 0);

    for (int i = 0; i < ntiles; i++) {
        const int n0 = i * FBN;
        if (i + 1 < ntiles) {
            fissue((i + 1) & 1, n0 + FBN);
            asm volatile("cp.async.wait_group 1;");
        } else {
            asm volatile("cp.async.wait_group 0;");
        }
        __syncthreads();

        const unsigned* Ksp = (const unsigned*)(fsm + (i & 1) * FSTAGE);
        const unsigned sbV  = sbd + (i & 1) * FSTAGE + KBUF;

        if (n0 <= rowmax) {
            // ---- S = Q K^T : 4 k16 steps x 8 n-subtiles ----
            float s[8][4];
#pragma unroll
            for (int nt = 0; nt < 8; nt++)
#pragma unroll
                for (int e = 0; e < 4; e++) s[nt][e] = 0.0f;

#pragma unroll
            for (int ks = 0; ks < 4; ks++) {
                unsigned bh[8][2];
#pragma unroll
                for (int nt = 0; nt < 8; nt++) {
                    int n = nt * 8 + l4;
                    bh[nt][0] = Ksp[n * KSW + ks * 8 + q];
                    bh[nt][1] = Ksp[n * KSW + ks * 8 + q + 4];
                }
#pragma unroll
                for (int nt = 0; nt < 8; nt++)
                    mma16f(s[nt], qh[ks], bh[nt]);
            }

            // ---- causal mask + row max ----
            float mt0 = -1e30f, mt1 = -1e30f;
#pragma unroll
            for (int nt = 0; nt < 8; nt++) {
#pragma unroll
                for (int e = 0; e < 2; e++) {
                    int col = n0 + nt * 8 + 2 * q + e;
                    if (col > r0)     s[nt][e]     = -1e30f;
                    if (col > r0 + 8) s[nt][2 + e] = -1e30f;
                    mt0 = fmaxf(mt0, s[nt][e]);
                    mt1 = fmaxf(mt1, s[nt][2 + e]);
                }
            }
            mt0 = fmaxf(mt0, __shfl_xor_sync(0xffffffff, mt0, 1));
            mt0 = fmaxf(mt0, __shfl_xor_sync(0xffffffff, mt0, 2));
            mt1 = fmaxf(mt1, __shfl_xor_sync(0xffffffff, mt1, 1));
            mt1 = fmaxf(mt1, __shfl_xor_sync(0xffffffff, mt1, 2));

            float mn0 = fmaxf(mcur0, mt0);
            float mn1 = fmaxf(mcur1, mt1);
            float cr0 = exp2f(mcur0 - mn0);
            float cr1 = exp2f(mcur1 - mn1);
            l0 *= cr0; l1 *= cr1;
#pragma unroll
            for (int d = 0; d < 8; d++) {
                oacc[d][0] *= cr0; oacc[d][1] *= cr0;
                oacc[d][2] *= cr1; oacc[d][3] *= cr1;
            }

#pragma unroll
            for (int nt = 0; nt < 8; nt++) {
                float p00 = exp2f(s[nt][0] - mn0);
                float p01 = exp2f(s[nt][1] - mn0);
                float p10 = exp2f(s[nt][2] - mn1);
                float p11 = exp2f(s[nt][3] - mn1);
                l0 += p00 + p01;
                l1 += p10 + p11;
                Psp[prow * PSW + nt * 4 + q]       = h2u(p00, p01);
                Psp[(prow + 8) * PSW + nt * 4 + q] = h2u(p10, p11);
            }
            mcur0 = mn0; mcur1 = mn1;
            __syncwarp();

            // ---- O += P V : 4 k16 steps, V b-frags via ldmatrix.trans ----
#pragma unroll
            for (int ks = 0; ks < 4; ks++) {
                unsigned a[4];
                a[0] = Psp[prow * PSW + ks * 8 + q];
                a[1] = Psp[(prow + 8) * PSW + ks * 8 + q];
                a[2] = Psp[prow * PSW + ks * 8 + q + 4];
                a[3] = Psp[(prow + 8) * PSW + ks * 8 + q + 4];
                int vrow = ks * 16 + (sub & 1) * 8 + r8;
#pragma unroll
                for (int dtp = 0; dtp < 4; dtp++) {
                    unsigned v0, v1, v2, v3;
                    unsigned addr = sbV + (unsigned)(vrow * (KSW * 4))
                                  + (unsigned)((dtp * 16 + (sub >> 1) * 8) * 2);
                    ldsm4t(v0, v1, v2, v3, addr);
                    unsigned b0[2] = {v0, v1};
                    unsigned b1[2] = {v2, v3};
                    mma16f(oacc[2 * dtp],     a, b0);
                    mma16f(oacc[2 * dtp + 1], a, b1);
                }
            }
        }
        __syncthreads();
    }

    l0 += __shfl_xor_sync(0xffffffff, l0, 1);
    l0 += __shfl_xor_sync(0xffffffff, l0, 2);
    l1 += __shfl_xor_sync(0xffffffff, l1, 1);
    l1 += __shfl_xor_sync(0xffffffff, l1, 2);
    float inv0 = 1.0f / l0;
    float inv1 = 1.0f / l1;

    unsigned* cw = (unsigned*)c16;
    size_t c0 = (size_t)(b * N_ + r0) * 1024 + h * 32;
    size_t c1 = c0 + (size_t)8 * 1024;
#pragma unroll
    for (int dt = 0; dt < 8; dt++) {
        cw[c0 + dt * 4 + q] = h2u(oacc[dt][0] * inv0, oacc[dt][1] * inv0);
        cw[c1 + dt * 4 + q] = h2u(oacc[dt][2] * inv1, oacc[dt][3] * inv1);
    }
}

// ===================================================================
// Launch
// ===================================================================
extern "C" void kernel_launch(void* const* d_in, const int* in_sizes, int n_in,
                              void* d_out, int out_size)
{
    const float* x  = (const float*)d_in[0];
    const float* Wq = (const float*)d_in[1];
    const float* Wk = (const float*)d_in[2];
    const float* Wv = (const float*)d_in[3];
    const float* Wo = (const float*)d_in[4];
    const float* bo = (const float*)d_in[5];
    float* out = (float*)d_out;

    __half *x16, *Wqkv16, *Wo16, *QKV16, *c16;
    cudaGetSymbolAddress((void**)&x16,    g_x16);
    cudaGetSymbolAddress((void**)&Wqkv16, g_Wqkv16);
    cudaGetSymbolAddress((void**)&Wo16,   g_Wo16);
    cudaGetSymbolAddress((void**)&QKV16,  g_QKV16);
    cudaGetSymbolAddress((void**)&c16,    g_c16);

    cudaFuncSetAttribute(gemm_f16, cudaFuncAttributeMaxDynamicSharedMemorySize,
                         GEMM_SMEMB);
    cudaFuncSetAttribute(flash16, cudaFuncAttributeMaxDynamicSharedMemorySize,
                         FLASH_SMEMB);

    const float qscale = 0.125f * 1.44269504f;

    // input conversions
    conv_x<<<(int)((size_t)M_ * DIN / 4 / 256), 256>>>((const float4*)x, (uint2*)x16);
    tconv_all<<<10240, 256>>>(Wq, Wk, Wv, Wo, Wqkv16, Wo16);

    // fused QKV projection -> fp16 (Q columns pre-scaled by qscale)
    gemm_f16<<<dim3(QKVW / 128, M_ / 128), 256, GEMM_SMEMB>>>(
        x16, Wqkv16, nullptr, QKV16, nullptr, QKVW, DIN, 2048, qscale);

    // attention
    flash16<<<dim3(N_ / FBM, H_, B_), 256, FLASH_SMEMB>>>(QKV16, c16);

    // output projection + bias -> fp32 out
    gemm_f16<<<dim3(DIN / 128, M_ / 128), 256, GEMM_SMEMB>>>(
        c16, Wo16, out, nullptr, bo, DIN, DOUT, 0, 1.0f);
}

// round 11
// speedup vs baseline: 10.3266x; 1.0455x over previous
#include <cuda_runtime.h>
#include <cuda_bf16.h>
#include <cuda_fp16.h>
#include <cstdint>
#include <math.h>

// Problem constants
#define B_   2
#define N_   2048
#define DIN  2048
#define DOUT 2048
#define H_   32
#define KV_  8
#define DH_  64
#define M_   (B_ * N_)          // 4096
#define QKVW 3072               // fused Q|K|V output width

// -------- scratch (allocation-free rule: __device__ globals) --------
__device__ __align__(16) __half g_x16[(size_t)M_ * DIN];          // A for QKV gemm
__device__ __align__(16) __half g_Wqkv16[(size_t)QKVW * DIN];     // [n][k]
__device__ __align__(16) __half g_Wo16[(size_t)DIN * DOUT];       // [n][k]
__device__ __align__(16) __half g_QKV16[(size_t)M_ * QKVW];       // fused fp16 proj out
__device__ __align__(16) __half g_c16[(size_t)M_ * DOUT];         // ctx fp16

// ---------------- helpers ----------------
__device__ __forceinline__ unsigned h2u(float a, float b) {
    __half2 h = __floats2half2_rn(a, b);
    return *reinterpret_cast<unsigned*>(&h);
}
__device__ __forceinline__ void mma16f(float c[4], const unsigned a[4], const unsigned b[2]) {
    asm volatile(
        "mma.sync.aligned.m16n8k16.row.col.f32.f16.f16.f32 "
        "{%0,%1,%2,%3}, {%4,%5,%6,%7}, {%8,%9}, {%0,%1,%2,%3};"
        : "+f"(c[0]), "+f"(c[1]), "+f"(c[2]), "+f"(c[3])
        : "r"(a[0]), "r"(a[1]), "r"(a[2]), "r"(a[3]), "r"(b[0]), "r"(b[1]));
}
__device__ __forceinline__ unsigned smem_u32(const void* p) {
    unsigned a;
    asm("{ .reg .u64 t; cvta.to.shared.u64 t, %1; cvt.u32.u64 %0, t; }" : "=r"(a) : "l"(p));
    return a;
}
__device__ __forceinline__ void ldsm4(unsigned& r0, unsigned& r1, unsigned& r2, unsigned& r3,
                                      unsigned addr) {
    asm volatile("ldmatrix.sync.aligned.m8n8.x4.shared.b16 {%0,%1,%2,%3}, [%4];"
                 : "=r"(r0), "=r"(r1), "=r"(r2), "=r"(r3) : "r"(addr));
}
__device__ __forceinline__ void ldsm4t(unsigned& r0, unsigned& r1, unsigned& r2, unsigned& r3,
                                       unsigned addr) {
    asm volatile("ldmatrix.sync.aligned.m8n8.x4.trans.shared.b16 {%0,%1,%2,%3}, [%4];"
                 : "=r"(r0), "=r"(r1), "=r"(r2), "=r"(r3) : "r"(addr));
}
__device__ __forceinline__ void cpa16(unsigned saddr, const void* g) {
    asm volatile("cp.async.cg.shared.global [%0], [%1], 16;" :: "r"(saddr), "l"(g));
}

// ===================================================================
// Conversion kernels (inputs only)
// ===================================================================
__global__ __launch_bounds__(256)
void conv_x(const float4* __restrict__ src, uint2* __restrict__ dst)
{
    size_t i = (size_t)(blockIdx.x * 256 + threadIdx.x);
    float4 v = src[i];
    dst[i] = make_uint2(h2u(v.x, v.y), h2u(v.z, v.w));
}

// all four weight transposes in one launch (linear region map)
__global__ __launch_bounds__(256)
void tconv_all(const float* __restrict__ Wq, const float* __restrict__ Wk,
               const float* __restrict__ Wv, const float* __restrict__ Wo,
               __half* __restrict__ Wqkv16, __half* __restrict__ Wo16)
{
    int bid = blockIdx.x;
    const float* src; __half* dst; int K, N, row_off;
    if (bid < 4096)      { src = Wq; dst = Wqkv16; K = DIN;  N = 2048; row_off = 0; }
    else if (bid < 5120) { src = Wk; dst = Wqkv16; K = DIN;  N = 512;  row_off = 2048; bid -= 4096; }
    else if (bid < 6144) { src = Wv; dst = Wqkv16; K = DIN;  N = 512;  row_off = 2560; bid -= 5120; }
    else                 { src = Wo; dst = Wo16;   K = DOUT; N = DIN;  row_off = 0;    bid -= 6144; }
    int ntn = N / 32;
    int n0 = (bid % ntn) * 32, k0 = (bid / ntn) * 32;

    __shared__ float t[32][33];
    int tx = threadIdx.x & 31, ty = threadIdx.x >> 5;
#pragma unroll
    for (int i = 0; i < 4; i++)
        t[ty + i * 8][tx] = src[(size_t)(k0 + ty + i * 8) * N + n0 + tx];
    __syncthreads();
#pragma unroll
    for (int i = 0; i < 4; i++) {
        int n = ty + i * 8;
        dst[(size_t)(row_off + n0 + n) * K + k0 + tx] = __float2half_rn(t[tx][n]);
    }
}

// ===================================================================
// fp16 GEMM (unchanged from R10): C[M,Nc] = A[M,K] @ B^T.
// block 128x128, KT=64, 8 warps (2x4), cp.async 2-stage + ldmatrix.
// ===================================================================
#define GST 36
#define BUFW (128 * GST)
#define BUFB (BUFW * 4)
#define STAGEB (2 * BUFB)
#define GEMM_SMEMB (2 * STAGEB)       // 73728 B

__global__ __launch_bounds__(256)
void gemm_f16(const __half* __restrict__ Ag, const __half* __restrict__ Bg,
              float* __restrict__ Cf, __half* __restrict__ Ch,
              const float* __restrict__ bias,
              int Nc, int K, int scaleCols, float scaleVal)
{
    extern __shared__ unsigned smw[];
    const unsigned sb = smem_u32(smw);

    const int tid  = threadIdx.x;
    const int lane = tid & 31;
    const int wid  = tid >> 5;
    const int wr   = (wid >> 2) * 64;
    const int wc   = (wid & 3) * 32;
    const int brow = blockIdx.y * 128;
    const int bcol = blockIdx.x * 128;
    const int q    = lane & 3;
    const int l4   = lane >> 2;
    const int Kw   = K >> 1;
    const int sub  = lane >> 3;
    const int r8   = lane & 7;

    const unsigned* Aw = (const unsigned*)Ag;
    const unsigned* Bw = (const unsigned*)Bg;

    float acc[4][4][4];
#pragma unroll
    for (int i = 0; i < 4; i++)
#pragma unroll
        for (int j = 0; j < 4; j++)
#pragma unroll
            for (int e = 0; e < 4; e++) acc[i][j][e] = 0.0f;

    const int nst = K / 64;

    auto issue = [&](int stage, int kw0) {
        unsigned sd = sb + stage * STAGEB;
#pragma unroll
        for (int p = 0; p < 4; p++) {
            int id = tid + p * 256;
            int r  = id >> 3;
            int c4 = (id & 7) * 4;
            unsigned o = (unsigned)(r * GST + c4) * 4;
            cpa16(sd + o,        Aw + (size_t)(brow + r) * Kw + kw0 + c4);
            cpa16(sd + BUFB + o, Bw + (size_t)(bcol + r) * Kw + kw0 + c4);
        }
        asm volatile("cp.async.commit_group;");
    };

    issue(0, 0);

    for (int i = 0; i < nst; i++) {
        if (i + 1 < nst) {
            issue((i + 1) & 1, (i + 1) * 32);
            asm volatile("cp.async.wait_group 1;");
        } else {
            asm volatile("cp.async.wait_group 0;");
        }
        __syncthreads();

        const unsigned sd = sb + (i & 1) * STAGEB;
        const unsigned sA = sd, sB = sd + BUFB;

#pragma unroll
        for (int ks2 = 0; ks2 < 32; ks2 += 8) {
            unsigned bh[4][2];
#pragma unroll
            for (int pr = 0; pr < 4; pr += 2) {
                int nrow = wc + (pr + (sub >> 1)) * 8 + r8;
                int colw = ks2 + (sub & 1) * 4;
                unsigned off = (unsigned)(nrow * GST + colw) * 4;
                ldsm4(bh[pr][0], bh[pr][1], bh[pr + 1][0], bh[pr + 1][1], sB + off);
            }
#pragma unroll
            for (int mt = 0; mt < 4; mt++) {
                int arow = wr + mt * 16 + (sub & 1) * 8 + r8;
                int colw = ks2 + (sub >> 1) * 4;
                unsigned off = (unsigned)(arow * GST + colw) * 4;
                unsigned ah[4];
                ldsm4(ah[0], ah[1], ah[2], ah[3], sA + off);
#pragma unroll
                for (int nt = 0; nt < 4; nt++)
                    mma16f(acc[mt][nt], ah, bh[nt]);
            }
        }
        __syncthreads();
    }

    if (Ch) {
        unsigned* Chw = (unsigned*)Ch;
        const int Ncw = Nc >> 1;
#pragma unroll
        for (int mt = 0; mt < 4; mt++) {
#pragma unroll
            for (int nt = 0; nt < 4; nt++) {
                int row = brow + wr + mt * 16 + l4;
                int col = bcol + wc + nt * 8 + 2 * q;
                float sc = (col < scaleCols) ? scaleVal : 1.0f;
                Chw[(size_t)row * Ncw + (col >> 1)] =
                    h2u(acc[mt][nt][0] * sc, acc[mt][nt][1] * sc);
                Chw[(size_t)(row + 8) * Ncw + (col >> 1)] =
                    h2u(acc[mt][nt][2] * sc, acc[mt][nt][3] * sc);
            }
        }
    } else {
#pragma unroll
        for (int mt = 0; mt < 4; mt++) {
#pragma unroll
            for (int nt = 0; nt < 4; nt++) {
                int row = brow + wr + mt * 16 + l4;
                int col = bcol + wc + nt * 8 + 2 * q;
                float b0 = 0.f, b1 = 0.f;
                if (bias) { b0 = bias[col]; b1 = bias[col + 1]; }
                *(float2*)(Cf + (size_t)row * Nc + col) =
                    make_float2(acc[mt][nt][0] + b0, acc[mt][nt][1] + b1);
                *(float2*)(Cf + (size_t)(row + 8) * Nc + col) =
                    make_float2(acc[mt][nt][2] + b0, acc[mt][nt][3] + b1);
            }
        }
    }
}

// ===================================================================
// Flash attention: FBM=128, FBN=64, 8 warps x 16 rows.
// cp.async double-buffered K/V tiles. P kept in REGISTERS (C-frag ==
// A-frag layout trick) — no Ps smem. Mask only diagonal tiles.
// ===================================================================
#define FBM 128
#define FBN 64
#define KSW 36                        // K/V row stride (words)
#define KBUF (FBN * KSW * 4)          // 9216 B per K (or V) buffer
#define FSTAGE (2 * KBUF)             // 18432 B per stage (K+V)
#define FLASH_SMEMB (2 * FSTAGE)      // 36864 B

__global__ __launch_bounds__(256)
void flash16(const __half* __restrict__ QKV16, __half* __restrict__ c16)
{
    extern __shared__ char fsm[];
    const unsigned sbd = smem_u32(fsm);

    const int tid  = threadIdx.x;
    const int lane = tid & 31;
    const int wid  = tid >> 5;              // 0..7
    const int q    = lane & 3;
    const int l4   = lane >> 2;
    const int sub  = lane >> 3;
    const int r8   = lane & 7;
    const int m0   = blockIdx.x * FBM;
    const int h    = blockIdx.y;
    const int b    = blockIdx.z;
    const int kv   = h >> 2;

    const int r0 = m0 + wid * 16 + l4;
    const int rowmin = m0 + wid * 16;       // lowest row owned by this warp
    const unsigned* W = (const unsigned*)QKV16;   // word ptr, row stride 1536

    // Q fragments (qscale pre-folded in gemm epilogue)
    unsigned qh[4][4];
    {
        size_t q0 = (size_t)(b * N_ + r0) * 1536 + h * 32;
        size_t q1 = q0 + (size_t)8 * 1536;
#pragma unroll
        for (int ks = 0; ks < 4; ks++) {
            qh[ks][0] = W[q0 + ks * 8 + q];
            qh[ks][1] = W[q1 + ks * 8 + q];
            qh[ks][2] = W[q0 + ks * 8 + q + 4];
            qh[ks][3] = W[q1 + ks * 8 + q + 4];
        }
    }

    float oacc[8][4];
#pragma unroll
    for (int d = 0; d < 8; d++)
#pragma unroll
        for (int e = 0; e < 4; e++) oacc[d][e] = 0.0f;
    float mcur0 = -1e30f, mcur1 = -1e30f, l0 = 0.0f, l1 = 0.0f;

    const int rowmax = rowmin + 15;
    const int ntiles = (m0 + FBM) / FBN;

    // stage issue: K/V tile of 64 rows x 8 uint4 each; 2 per thread per tensor
    auto fissue = [&](int stage, int n0) {
        unsigned sd = sbd + stage * FSTAGE;
#pragma unroll
        for (int p = 0; p < 2; p++) {
            int id = tid + p * 256;
            int r  = id >> 3;
            int w4 = (id & 7) * 4;
            size_t rowbase = (size_t)(b * N_ + n0 + r) * 1536 + kv * 32;
            unsigned o = (unsigned)(r * KSW + w4) * 4;
            cpa16(sd + o,        W + rowbase + 1024 + w4);   // K
            cpa16(sd + KBUF + o, W + rowbase + 1280 + w4);   // V
        }
        asm volatile("cp.async.commit_group;");
    };

    fissue(0, 0);

    for (int i = 0; i < ntiles; i++) {
        const int n0 = i * FBN;
        if (i + 1 < ntiles) {
            fissue((i + 1) & 1, n0 + FBN);
            asm volatile("cp.async.wait_group 1;");
        } else {
            asm volatile("cp.async.wait_group 0;");
        }
        __syncthreads();

        const unsigned* Ksp = (const unsigned*)(fsm + (i & 1) * FSTAGE);
        const unsigned sbV  = sbd + (i & 1) * FSTAGE + KBUF;

        if (n0 <= rowmax) {
            // ---- S = Q K^T : 4 k16 steps x 8 n-subtiles ----
            float s[8][4];
#pragma unroll
            for (int nt = 0; nt < 8; nt++)
#pragma unroll
                for (int e = 0; e < 4; e++) s[nt][e] = 0.0f;

#pragma unroll
            for (int ks = 0; ks < 4; ks++) {
                unsigned bh[8][2];
#pragma unroll
                for (int nt = 0; nt < 8; nt++) {
                    int n = nt * 8 + l4;
                    bh[nt][0] = Ksp[n * KSW + ks * 8 + q];
                    bh[nt][1] = Ksp[n * KSW + ks * 8 + q + 4];
                }
#pragma unroll
                for (int nt = 0; nt < 8; nt++)
                    mma16f(s[nt], qh[ks], bh[nt]);
            }

            // ---- row max (mask only on diagonal tiles) ----
            float mt0 = -1e30f, mt1 = -1e30f;
            if (n0 + FBN - 1 > rowmin) {        // tile crosses the diagonal
#pragma unroll
                for (int nt = 0; nt < 8; nt++) {
#pragma unroll
                    for (int e = 0; e < 2; e++) {
                        int col = n0 + nt * 8 + 2 * q + e;
                        if (col > r0)     s[nt][e]     = -1e30f;
                        if (col > r0 + 8) s[nt][2 + e] = -1e30f;
                        mt0 = fmaxf(mt0, s[nt][e]);
                        mt1 = fmaxf(mt1, s[nt][2 + e]);
                    }
                }
            } else {                            // fully unmasked
#pragma unroll
                for (int nt = 0; nt < 8; nt++) {
                    mt0 = fmaxf(mt0, fmaxf(s[nt][0], s[nt][1]));
                    mt1 = fmaxf(mt1, fmaxf(s[nt][2], s[nt][3]));
                }
            }
            mt0 = fmaxf(mt0, __shfl_xor_sync(0xffffffff, mt0, 1));
            mt0 = fmaxf(mt0, __shfl_xor_sync(0xffffffff, mt0, 2));
            mt1 = fmaxf(mt1, __shfl_xor_sync(0xffffffff, mt1, 1));
            mt1 = fmaxf(mt1, __shfl_xor_sync(0xffffffff, mt1, 2));

            float mn0 = fmaxf(mcur0, mt0);
            float mn1 = fmaxf(mcur1, mt1);
            float cr0 = exp2f(mcur0 - mn0);
            float cr1 = exp2f(mcur1 - mn1);
            l0 *= cr0; l1 *= cr1;
#pragma unroll
            for (int d = 0; d < 8; d++) {
                oacc[d][0] *= cr0; oacc[d][1] *= cr0;
                oacc[d][2] *= cr1; oacc[d][3] *= cr1;
            }

            // ---- P in registers: C-frag -> A-frag layout ----
            unsigned pa[8][2];
#pragma unroll
            for (int nt = 0; nt < 8; nt++) {
                float p00 = exp2f(s[nt][0] - mn0);
                float p01 = exp2f(s[nt][1] - mn0);
                float p10 = exp2f(s[nt][2] - mn1);
                float p11 = exp2f(s[nt][3] - mn1);
                l0 += p00 + p01;
                l1 += p10 + p11;
                pa[nt][0] = h2u(p00, p01);      // rows r0,   cols 2q,2q+1
                pa[nt][1] = h2u(p10, p11);      // rows r0+8
            }
            mcur0 = mn0; mcur1 = mn1;

            // ---- O += P V : 4 k16 steps, V b-frags via ldmatrix.trans ----
#pragma unroll
            for (int ks = 0; ks < 4; ks++) {
                unsigned a[4];
                a[0] = pa[2 * ks][0];
                a[1] = pa[2 * ks][1];
                a[2] = pa[2 * ks + 1][0];
                a[3] = pa[2 * ks + 1][1];
                int vrow = ks * 16 + (sub & 1) * 8 + r8;
#pragma unroll
                for (int dtp = 0; dtp < 4; dtp++) {
                    unsigned v0, v1, v2, v3;
                    unsigned addr = sbV + (unsigned)(vrow * (KSW * 4))
                                  + (unsigned)((dtp * 16 + (sub >> 1) * 8) * 2);
                    ldsm4t(v0, v1, v2, v3, addr);
                    unsigned b0[2] = {v0, v1};
                    unsigned b1[2] = {v2, v3};
                    mma16f(oacc[2 * dtp],     a, b0);
                    mma16f(oacc[2 * dtp + 1], a, b1);
                }
            }
        }
        __syncthreads();
    }

    l0 += __shfl_xor_sync(0xffffffff, l0, 1);
    l0 += __shfl_xor_sync(0xffffffff, l0, 2);
    l1 += __shfl_xor_sync(0xffffffff, l1, 1);
    l1 += __shfl_xor_sync(0xffffffff, l1, 2);
    float inv0 = 1.0f / l0;
    float inv1 = 1.0f / l1;

    unsigned* cw = (unsigned*)c16;
    size_t c0 = (size_t)(b * N_ + r0) * 1024 + h * 32;
    size_t c1 = c0 + (size_t)8 * 1024;
#pragma unroll
    for (int dt = 0; dt < 8; dt++) {
        cw[c0 + dt * 4 + q] = h2u(oacc[dt][0] * inv0, oacc[dt][1] * inv0);
        cw[c1 + dt * 4 + q] = h2u(oacc[dt][2] * inv1, oacc[dt][3] * inv1);
    }
}

// ===================================================================
// Launch
// ===================================================================
extern "C" void kernel_launch(void* const* d_in, const int* in_sizes, int n_in,
                              void* d_out, int out_size)
{
    const float* x  = (const float*)d_in[0];
    const float* Wq = (const float*)d_in[1];
    const float* Wk = (const float*)d_in[2];
    const float* Wv = (const float*)d_in[3];
    const float* Wo = (const float*)d_in[4];
    const float* bo = (const float*)d_in[5];
    float* out = (float*)d_out;

    __half *x16, *Wqkv16, *Wo16, *QKV16, *c16;
    cudaGetSymbolAddress((void**)&x16,    g_x16);
    cudaGetSymbolAddress((void**)&Wqkv16, g_Wqkv16);
    cudaGetSymbolAddress((void**)&Wo16,   g_Wo16);
    cudaGetSymbolAddress((void**)&QKV16,  g_QKV16);
    cudaGetSymbolAddress((void**)&c16,    g_c16);

    cudaFuncSetAttribute(gemm_f16, cudaFuncAttributeMaxDynamicSharedMemorySize,
                         GEMM_SMEMB);
    cudaFuncSetAttribute(flash16, cudaFuncAttributeMaxDynamicSharedMemorySize,
                         FLASH_SMEMB);

    const float qscale = 0.125f * 1.44269504f;

    // input conversions
    conv_x<<<(int)((size_t)M_ * DIN / 4 / 256), 256>>>((const float4*)x, (uint2*)x16);
    tconv_all<<<10240, 256>>>(Wq, Wk, Wv, Wo, Wqkv16, Wo16);

    // fused QKV projection -> fp16 (Q columns pre-scaled by qscale)
    gemm_f16<<<dim3(QKVW / 128, M_ / 128), 256, GEMM_SMEMB>>>(
        x16, Wqkv16, nullptr, QKV16, nullptr, QKVW, DIN, 2048, qscale);

    // attention
    flash16<<<dim3(N_ / FBM, H_, B_), 256, FLASH_SMEMB>>>(QKV16, c16);

    // output projection + bias -> fp32 out
    gemm_f16<<<dim3(DIN / 128, M_ / 128), 256, GEMM_SMEMB>>>(
        c16, Wo16, out, nullptr, bo, DIN, DOUT, 0, 1.0f);
}